// round 10
// baseline (speedup 1.0000x reference)
#include <cuda_runtime.h>
#include <cuda_fp16.h>
#include <math.h>
#include <float.h>
#include <stdint.h>

// Problem constants (GAT_38585986187787)
#define MAX_NODES 100000
#define MAX_EDGES 1600000
#define D_IN 64
#define HEADS 4
#define HC 256   // HEADS * C_OUT
#define SCAN_B 1024
#define MAX_SCAN_BLOCKS 128
#define AGG_NODES 32   // nodes per fused block

#define SAP 132   // agg smem row stride (uint32): 528B/row -> 4-bank row spacing
#define SWN 264   // W smem row stride (halves):  528B/row -> 4-bank row spacing

// ---------------------------------------------------------------------------
// Device scratch
// ---------------------------------------------------------------------------
__device__ __half g_x16[(size_t)MAX_NODES * D_IN];  // 12.8 MB  x in fp16 (L2-resident)
__device__ float g_asrc[MAX_NODES * HEADS];
__device__ float g_adst[MAX_NODES * HEADS];
__device__ float g_was[HEADS * D_IN];               // W_h @ att_src_h
__device__ float g_wad[HEADS * D_IN];               // W_h @ att_dst_h
__device__ int   g_cnt[MAX_NODES];
__device__ int   g_off[MAX_NODES + 1];
__device__ int   g_cur[MAX_NODES];
__device__ int   g_srclist[MAX_EDGES];
__device__ int   g_bsum[MAX_SCAN_BLOCKS];
__device__ int   g_bpre[MAX_SCAN_BLOCKS];
__device__ int   g_is64;

__device__ __forceinline__ long long load_edge(const void* ei, int is64, size_t idx) {
    if (is64) return ((const long long*)ei)[idx];
    return (long long)(((const int*)ei)[idx]);
}

__device__ __forceinline__ float leaky(float v) {
    return (v >= 0.f) ? v : 0.2f * v;
}

// ---------------------------------------------------------------------------
// 1. Init: detect dtype, zero counters, block 0 computes projected att vecs
// ---------------------------------------------------------------------------
__global__ void init_kernel(const void* ei, const float* __restrict__ W,
                            const float* __restrict__ att_src,
                            const float* __restrict__ att_dst, int n) {
    int idx = blockIdx.x * blockDim.x + threadIdx.x;
    if (idx == 0) {
        const unsigned long long* p = (const unsigned long long*)ei;
        bool ok = true;
#pragma unroll
        for (int i = 0; i < 16; i++) ok = ok && (p[i] < (unsigned long long)MAX_NODES);
        g_is64 = ok ? 1 : 0;
    }
    if (idx < n) g_cnt[idx] = 0;
    if (blockIdx.x == 0) {
        for (int o = threadIdx.x; o < 2 * HEADS * D_IN; o += blockDim.x) {
            int kind = o >> 8;
            int h = (o >> 6) & 3;
            int c = o & 63;
            const float* av = (kind ? att_dst : att_src) + h * 64;
            float s = 0.f;
#pragma unroll 8
            for (int j = 0; j < 64; j++) s += W[(size_t)c * HC + h * 64 + j] * av[j];
            if (kind) g_wad[h * 64 + c] = s;
            else      g_was[h * 64 + c] = s;
        }
    }
}

// ---------------------------------------------------------------------------
// 2. Count in-degrees (4 edges per thread)
// ---------------------------------------------------------------------------
__global__ void count_kernel(const void* __restrict__ ei, int E) {
    int e = (blockIdx.x * blockDim.x + threadIdx.x) * 4;
    if (e >= E) return;
    int is64 = g_is64;
    if (e + 3 < E) {
        int d[4];
        if (is64) {
            longlong2 p0 = *(const longlong2*)((const long long*)ei + (size_t)E + e);
            longlong2 p1 = *(const longlong2*)((const long long*)ei + (size_t)E + e + 2);
            d[0] = (int)p0.x; d[1] = (int)p0.y; d[2] = (int)p1.x; d[3] = (int)p1.y;
        } else {
            int4 p = *(const int4*)((const int*)ei + (size_t)E + e);
            d[0] = p.x; d[1] = p.y; d[2] = p.z; d[3] = p.w;
        }
#pragma unroll
        for (int k = 0; k < 4; k++) atomicAdd(&g_cnt[d[k]], 1);
    } else {
        for (int k = e; k < E; k++)
            atomicAdd(&g_cnt[(int)load_edge(ei, is64, (size_t)E + k)], 1);
    }
}

// ---------------------------------------------------------------------------
// 3a. Block-local exclusive scan
// ---------------------------------------------------------------------------
__global__ void scan1_kernel(int N) {
    int t = threadIdx.x;
    int i = blockIdx.x * SCAN_B + t;
    int lane = t & 31, wid = t >> 5;

    int v = (i < N) ? g_cnt[i] : 0;
    int x = v;
#pragma unroll
    for (int off = 1; off < 32; off <<= 1) {
        int u = __shfl_up_sync(0xffffffffu, x, off);
        if (lane >= off) x += u;
    }
    __shared__ int wsum[32];
    if (lane == 31) wsum[wid] = x;
    __syncthreads();
    if (wid == 0) {
        int y = wsum[lane];
#pragma unroll
        for (int off = 1; off < 32; off <<= 1) {
            int u = __shfl_up_sync(0xffffffffu, y, off);
            if (lane >= off) y += u;
        }
        wsum[lane] = y;
    }
    __syncthreads();
    int base = (wid > 0) ? wsum[wid - 1] : 0;
    int incl = base + x;
    if (i < N) g_off[i] = incl - v;
    if (t == SCAN_B - 1) g_bsum[blockIdx.x] = incl;
}

// ---------------------------------------------------------------------------
// 4. Attention scores + fp16 convert (4 nodes/warp, 8-lane groups).
// ---------------------------------------------------------------------------
__global__ void att_kernel(const float* __restrict__ x, int N) {
    int gw = (blockIdx.x * blockDim.x + threadIdx.x) >> 5;
    int lane = threadIdx.x & 31;
    int g = lane >> 3, l8 = lane & 7;
    int node = gw * 4 + g;
    if (node >= N) return;

    const float* xr = x + (size_t)node * D_IN + l8 * 8;
    float4 v0 = *(const float4*)xr;
    float4 v1 = *(const float4*)(xr + 4);

    __half2 h0 = __floats2half2_rn(v0.x, v0.y);
    __half2 h1 = __floats2half2_rn(v0.z, v0.w);
    __half2 h2 = __floats2half2_rn(v1.x, v1.y);
    __half2 h3 = __floats2half2_rn(v1.z, v1.w);
    uint4 pk = make_uint4(*(uint32_t*)&h0, *(uint32_t*)&h1, *(uint32_t*)&h2, *(uint32_t*)&h3);
    *(uint4*)(g_x16 + (size_t)node * D_IN + l8 * 8) = pk;

    float ps[4], pd[4];
#pragma unroll
    for (int h = 0; h < 4; h++) {
        const float* ws = g_was + h * 64 + l8 * 8;
        const float* wd = g_wad + h * 64 + l8 * 8;
        float4 s0 = *(const float4*)ws, s1 = *(const float4*)(ws + 4);
        float4 d0 = *(const float4*)wd, d1 = *(const float4*)(wd + 4);
        ps[h] = v0.x * s0.x + v0.y * s0.y + v0.z * s0.z + v0.w * s0.w
              + v1.x * s1.x + v1.y * s1.y + v1.z * s1.z + v1.w * s1.w;
        pd[h] = v0.x * d0.x + v0.y * d0.y + v0.z * d0.z + v0.w * d0.w
              + v1.x * d1.x + v1.y * d1.y + v1.z * d1.z + v1.w * d1.w;
    }
#pragma unroll
    for (int off = 4; off > 0; off >>= 1) {
#pragma unroll
        for (int h = 0; h < 4; h++) {
            ps[h] += __shfl_xor_sync(0xffffffffu, ps[h], off, 8);
            pd[h] += __shfl_xor_sync(0xffffffffu, pd[h], off, 8);
        }
    }
    if (l8 == 0) {
        *(float4*)(g_asrc + node * HEADS) = make_float4(ps[0], ps[1], ps[2], ps[3]);
        *(float4*)(g_adst + node * HEADS) = make_float4(pd[0], pd[1], pd[2], pd[3]);
    }
}

// ---------------------------------------------------------------------------
// 3b/3c. Scan block sums + add bases
// ---------------------------------------------------------------------------
__global__ void scan2_kernel(int nb, int N, int E) {
    int t = threadIdx.x, lane = t & 31, wid = t >> 5;
    int v = (t < nb) ? g_bsum[t] : 0;
    int x = v;
#pragma unroll
    for (int off = 1; off < 32; off <<= 1) {
        int u = __shfl_up_sync(0xffffffffu, x, off);
        if (lane >= off) x += u;
    }
    __shared__ int ws[4];
    __shared__ int wpre[4];
    if (lane == 31) ws[wid] = x;
    __syncthreads();
    if (t == 0) {
        int s = 0;
#pragma unroll
        for (int k = 0; k < 4; k++) { wpre[k] = s; s += ws[k]; }
    }
    __syncthreads();
    int incl = wpre[wid] + x;
    if (t < nb) g_bpre[t] = incl - v;
    if (t == 0) g_off[N] = E;
}

__global__ void scan3_kernel(int N) {
    int i = blockIdx.x * SCAN_B + threadIdx.x;
    if (i < N) {
        int o = g_off[i] + g_bpre[blockIdx.x];
        g_off[i] = o;
        g_cur[i] = o;
    }
}

// ---------------------------------------------------------------------------
// 5. Scatter src ids into CSR slots (4 edges per thread)
// ---------------------------------------------------------------------------
__global__ void scatter_kernel(const void* __restrict__ ei, int E) {
    int e = (blockIdx.x * blockDim.x + threadIdx.x) * 4;
    if (e >= E) return;
    int is64 = g_is64;
    if (e + 3 < E) {
        int s[4], d[4];
        if (is64) {
            longlong2 ps0 = *(const longlong2*)((const long long*)ei + e);
            longlong2 ps1 = *(const longlong2*)((const long long*)ei + e + 2);
            longlong2 pd0 = *(const longlong2*)((const long long*)ei + (size_t)E + e);
            longlong2 pd1 = *(const longlong2*)((const long long*)ei + (size_t)E + e + 2);
            s[0] = (int)ps0.x; s[1] = (int)ps0.y; s[2] = (int)ps1.x; s[3] = (int)ps1.y;
            d[0] = (int)pd0.x; d[1] = (int)pd0.y; d[2] = (int)pd1.x; d[3] = (int)pd1.y;
        } else {
            int4 ps = *(const int4*)((const int*)ei + e);
            int4 pd = *(const int4*)((const int*)ei + (size_t)E + e);
            s[0] = ps.x; s[1] = ps.y; s[2] = ps.z; s[3] = ps.w;
            d[0] = pd.x; d[1] = pd.y; d[2] = pd.z; d[3] = pd.w;
        }
#pragma unroll
        for (int k = 0; k < 4; k++) {
            int pos = atomicAdd(&g_cur[d[k]], 1);
            g_srclist[pos] = s[k];
        }
    } else {
        for (int k = e; k < E; k++) {
            int s = (int)load_edge(ei, is64, k);
            int d = (int)load_edge(ei, is64, (size_t)E + k);
            int pos = atomicAdd(&g_cur[d], 1);
            g_srclist[pos] = s;
        }
    }
}

// ---------------------------------------------------------------------------
// 6. FUSED aggregate + output GEMM.  Block = 256 thr (8 warps), 32 nodes.
//    Phase 1: warps dynamically grab nodes (smem counter), aggregate in
//             x-space exactly like r9 agg, write normalized fp16 rows to smem.
//    Phase 2: [32,256] @ per-head W[64,64] via ldmatrix + m16n8k16 MMA,
//             warp = (head, n-half); epilogue adds bias, stores fp32 out.
// ---------------------------------------------------------------------------
__global__ void __launch_bounds__(256, 2)
fused_kernel(const float* __restrict__ W, const float* __restrict__ bias,
             float* __restrict__ out, int N) {
    extern __shared__ uint32_t sm[];
    uint32_t* sAgg = sm;                                  // 32 x SAP uint32
    __half*  sBh  = (__half*)(sm + AGG_NODES * SAP);      // 64 x SWN halves
    float4*  swe  = (float4*)(sBh + 64 * SWN);            // [8][32]
    int*     ssid = (int*)(swe + 8 * 32);                 // [8][32]
    __shared__ int s_next;

    int t = threadIdx.x;
    int lane = t & 31;
    int wl = t >> 5;
    int row0 = blockIdx.x * AGG_NODES;

    // ---- Phase 0: stage W as [k][n] halves; init node counter ----
#pragma unroll
    for (int i = 0; i < 16; i++) {
        int idx4 = t + i * 256;
        int k = idx4 >> 6, c = (idx4 & 63) * 4;
        float4 v = *(const float4*)(W + (size_t)k * HC + c);
        __half2* q = (__half2*)(sBh + k * SWN + c);
        q[0] = __floats2half2_rn(v.x, v.y);
        q[1] = __floats2half2_rn(v.z, v.w);
    }
    if (t == 0) s_next = 8;
    __syncthreads();

    // ---- Phase 1: aggregate nodes into sAgg rows ----
    int local = wl;
    while (local < AGG_NODES) {
        int node = row0 + local;
        uint32_t* aggrow = sAgg + local * SAP;

        int beg = 0, end = 0;
        if (node < N) { beg = g_off[node]; end = g_off[node + 1]; }

        if (beg == end) {
#pragma unroll
            for (int h = 0; h < 4; h++) aggrow[h * 32 + lane] = 0u;
        } else {
            float4 ad4 = *(const float4*)(g_adst + node * HEADS);
            float4 den4 = make_float4(0.f, 0.f, 0.f, 0.f);
            float acc[8];
#pragma unroll
            for (int k = 0; k < 8; k++) acc[k] = 0.f;

            for (int base = beg; base < end; base += 32) {
                int c = min(end - base, 32);
                if (lane < c) {
                    int s = g_srclist[base + lane];
                    float4 as = *(const float4*)(g_asrc + s * HEADS);
                    float4 we;
                    we.x = __expf(leaky(as.x + ad4.x));
                    we.y = __expf(leaky(as.y + ad4.y));
                    we.z = __expf(leaky(as.z + ad4.z));
                    we.w = __expf(leaky(as.w + ad4.w));
                    den4.x += we.x; den4.y += we.y; den4.z += we.z; den4.w += we.w;
                    swe[wl * 32 + lane] = we;
                    ssid[wl * 32 + lane] = s;
                }
                __syncwarp();

                uint32_t x0 = *(const uint32_t*)(g_x16 + (size_t)ssid[wl * 32] * D_IN + lane * 2);
                for (int j = 0; j < c; j++) {
                    uint32_t x1 = 0;
                    if (j + 1 < c)
                        x1 = *(const uint32_t*)(g_x16 + (size_t)ssid[wl * 32 + j + 1] * D_IN + lane * 2);
                    float4 we = swe[wl * 32 + j];
                    float2 xv = __half22float2(*(__half2*)&x0);
                    acc[0] += we.x * xv.x; acc[1] += we.x * xv.y;
                    acc[2] += we.y * xv.x; acc[3] += we.y * xv.y;
                    acc[4] += we.z * xv.x; acc[5] += we.z * xv.y;
                    acc[6] += we.w * xv.x; acc[7] += we.w * xv.y;
                    x0 = x1;
                }
                __syncwarp();
            }

#pragma unroll
            for (int off = 16; off > 0; off >>= 1) {
                den4.x += __shfl_xor_sync(0xffffffffu, den4.x, off);
                den4.y += __shfl_xor_sync(0xffffffffu, den4.y, off);
                den4.z += __shfl_xor_sync(0xffffffffu, den4.z, off);
                den4.w += __shfl_xor_sync(0xffffffffu, den4.w, off);
            }
            float ix = 1.f / (den4.x + 1e-16f);
            float iy = 1.f / (den4.y + 1e-16f);
            float iz = 1.f / (den4.z + 1e-16f);
            float iw = 1.f / (den4.w + 1e-16f);
            __half2 r0 = __floats2half2_rn(acc[0] * ix, acc[1] * ix);
            __half2 r1 = __floats2half2_rn(acc[2] * iy, acc[3] * iy);
            __half2 r2 = __floats2half2_rn(acc[4] * iz, acc[5] * iz);
            __half2 r3 = __floats2half2_rn(acc[6] * iw, acc[7] * iw);
            aggrow[0 * 32 + lane] = *(uint32_t*)&r0;
            aggrow[1 * 32 + lane] = *(uint32_t*)&r1;
            aggrow[2 * 32 + lane] = *(uint32_t*)&r2;
            aggrow[3 * 32 + lane] = *(uint32_t*)&r3;
        }

        int nxt = 0;
        if (lane == 0) nxt = atomicAdd(&s_next, 1);
        local = __shfl_sync(0xffffffffu, nxt, 0);
    }
    __syncthreads();

    // ---- Phase 2: [32,256] GEMM. warp -> head h = wl&3, n-half = wl>>2 ----
    int h = wl & 3;
    int nh = wl >> 2;          // 0 or 1: output cols h*64 + nh*32 + [0,32)

    uint32_t smem_base = (uint32_t)__cvta_generic_to_shared(sm);
    uint32_t sB_base = smem_base + AGG_NODES * SAP * 4;

    int l8 = lane & 7;
    int lrow8 = (lane >> 3) & 1;
    int lk8 = (lane >> 4) & 1;

    uint32_t aAddr[2];
#pragma unroll
    for (int mt = 0; mt < 2; mt++) {
        int r = mt * 16 + l8 + lrow8 * 8;
        aAddr[mt] = smem_base + r * (SAP * 4) + (h * 64 + lk8 * 8) * 2;
    }
    uint32_t bAddr[2];
#pragma unroll
    for (int ntp = 0; ntp < 2; ntp++) {
        int krow = l8 + lrow8 * 8;
        bAddr[ntp] = sB_base + krow * (SWN * 2) + (h * 64 + nh * 32 + ntp * 16 + lk8 * 8) * 2;
    }

    float acc[2][4][4];
#pragma unroll
    for (int mt = 0; mt < 2; mt++)
#pragma unroll
        for (int nt = 0; nt < 4; nt++)
#pragma unroll
            for (int k = 0; k < 4; k++) acc[mt][nt][k] = 0.f;

#pragma unroll
    for (int kc = 0; kc < 4; kc++) {
        uint32_t a[2][4];
#pragma unroll
        for (int mt = 0; mt < 2; mt++) {
            asm volatile(
                "ldmatrix.sync.aligned.m8n8.x4.shared.b16 {%0,%1,%2,%3}, [%4];"
                : "=r"(a[mt][0]), "=r"(a[mt][1]), "=r"(a[mt][2]), "=r"(a[mt][3])
                : "r"(aAddr[mt] + kc * 32));
        }
        uint32_t b[2][4];
#pragma unroll
        for (int ntp = 0; ntp < 2; ntp++) {
            asm volatile(
                "ldmatrix.sync.aligned.m8n8.x4.trans.shared.b16 {%0,%1,%2,%3}, [%4];"
                : "=r"(b[ntp][0]), "=r"(b[ntp][1]), "=r"(b[ntp][2]), "=r"(b[ntp][3])
                : "r"(bAddr[ntp] + kc * 16 * (SWN * 2)));
        }
#pragma unroll
        for (int mt = 0; mt < 2; mt++)
#pragma unroll
            for (int nt = 0; nt < 4; nt++) {
                float* c = acc[mt][nt];
                uint32_t b0 = b[nt >> 1][(nt & 1) * 2 + 0];
                uint32_t b1 = b[nt >> 1][(nt & 1) * 2 + 1];
                asm volatile(
                    "mma.sync.aligned.m16n8k16.row.col.f32.f16.f16.f32 "
                    "{%0,%1,%2,%3}, {%4,%5,%6,%7}, {%8,%9}, {%0,%1,%2,%3};"
                    : "+f"(c[0]), "+f"(c[1]), "+f"(c[2]), "+f"(c[3])
                    : "r"(a[mt][0]), "r"(a[mt][1]), "r"(a[mt][2]), "r"(a[mt][3]),
                      "r"(b0), "r"(b1));
            }
    }

    int qr = lane >> 2;
    int ql = lane & 3;
#pragma unroll
    for (int mt = 0; mt < 2; mt++) {
        int r_lo = row0 + mt * 16 + qr;
#pragma unroll
        for (int nt = 0; nt < 4; nt++) {
            int col = h * 64 + nh * 32 + nt * 8 + 2 * ql;
            float2 bb = *(const float2*)(bias + col);
            const float* c = acc[mt][nt];
            if (r_lo < N)
                *(float2*)(out + (size_t)r_lo * HC + col) = make_float2(c[0] + bb.x, c[1] + bb.y);
            if (r_lo + 8 < N)
                *(float2*)(out + (size_t)(r_lo + 8) * HC + col) = make_float2(c[2] + bb.x, c[3] + bb.y);
        }
    }
}

// ---------------------------------------------------------------------------
// Launch.  att_kernel is the 4th launch (ncu profiles launch #4).
// ---------------------------------------------------------------------------
extern "C" void kernel_launch(void* const* d_in, const int* in_sizes, int n_in,
                              void* d_out, int out_size) {
    const float* x        = (const float*)d_in[0];
    const void*  ei       = (const void*)d_in[1];
    const float* W        = (const float*)d_in[2];
    const float* att_src  = (const float*)d_in[3];
    const float* att_dst  = (const float*)d_in[4];
    const float* bias     = (const float*)d_in[5];
    float* out = (float*)d_out;

    int N = in_sizes[0] / D_IN;
    int E = in_sizes[1] / 2;

    init_kernel<<<(N + 255) / 256, 256>>>(ei, W, att_src, att_dst, N);  // 1
    count_kernel<<<(E / 4 + 256) / 256, 256>>>(ei, E);                  // 2

    int nb = (N + SCAN_B - 1) / SCAN_B;
    scan1_kernel<<<nb, SCAN_B>>>(N);                                    // 3

    int att_warps = (N + 3) / 4;
    att_kernel<<<(att_warps * 32 + 255) / 256, 256>>>(x, N);            // 4 (profiled)

    scan2_kernel<<<1, 128>>>(nb, N, E);                                 // 5
    scan3_kernel<<<nb, SCAN_B>>>(N);                                    // 6
    scatter_kernel<<<(E / 4 + 256) / 256, 256>>>(ei, E);                // 7

    size_t smem = (size_t)AGG_NODES * SAP * 4 + (size_t)64 * SWN * 2
                + 8 * 32 * sizeof(float4) + 8 * 32 * sizeof(int);       // ~56 KB
    cudaFuncSetAttribute(fused_kernel, cudaFuncAttributeMaxDynamicSharedMemorySize, (int)smem);
    fused_kernel<<<(N + AGG_NODES - 1) / AGG_NODES, 256, smem>>>(W, bias, out, N);  // 8
}

// round 11
// speedup vs baseline: 1.2947x; 1.2947x over previous
#include <cuda_runtime.h>
#include <cuda_fp16.h>
#include <math.h>
#include <float.h>
#include <stdint.h>

// Problem constants (GAT_38585986187787)
#define MAX_NODES 100000
#define MAX_EDGES 1600000
#define D_IN 64
#define HEADS 4
#define HC 256   // HEADS * C_OUT
#define SCAN_B 1024
#define MAX_SCAN_BLOCKS 128

#define SAP 132   // agg smem row stride (uint32): 528B/row -> 4-bank row spacing
#define SWN 264   // W smem row stride (halves):  528B/row -> 4-bank row spacing

// ---------------------------------------------------------------------------
// Device scratch
// ---------------------------------------------------------------------------
__device__ __half g_x16[(size_t)MAX_NODES * D_IN];  // 12.8 MB  x in fp16 (L2-resident)
__device__ __half g_agg[(size_t)MAX_NODES * HC];    // 51.2 MB  normalized weighted sums
__device__ float g_asrc[MAX_NODES * HEADS];
__device__ float g_adst[MAX_NODES * HEADS];
__device__ float g_was[HEADS * D_IN];               // W_h @ att_src_h
__device__ float g_wad[HEADS * D_IN];               // W_h @ att_dst_h
__device__ int   g_cnt[MAX_NODES];
__device__ int   g_off[MAX_NODES + 1];
__device__ int   g_cur[MAX_NODES];
__device__ int   g_srclist[MAX_EDGES];
__device__ int   g_bsum[MAX_SCAN_BLOCKS];
__device__ int   g_bpre[MAX_SCAN_BLOCKS];
__device__ int   g_is64;

__device__ __forceinline__ long long load_edge(const void* ei, int is64, size_t idx) {
    if (is64) return ((const long long*)ei)[idx];
    return (long long)(((const int*)ei)[idx]);
}

__device__ __forceinline__ float leaky(float v) {
    return (v >= 0.f) ? v : 0.2f * v;
}

// ---------------------------------------------------------------------------
// 1. Init: detect dtype, zero counters, block 0 computes projected att vecs
// ---------------------------------------------------------------------------
__global__ void init_kernel(const void* ei, const float* __restrict__ W,
                            const float* __restrict__ att_src,
                            const float* __restrict__ att_dst, int n) {
    int idx = blockIdx.x * blockDim.x + threadIdx.x;
    if (idx == 0) {
        const unsigned long long* p = (const unsigned long long*)ei;
        bool ok = true;
#pragma unroll
        for (int i = 0; i < 16; i++) ok = ok && (p[i] < (unsigned long long)MAX_NODES);
        g_is64 = ok ? 1 : 0;
    }
    if (idx < n) g_cnt[idx] = 0;
    if (blockIdx.x == 0) {
        for (int o = threadIdx.x; o < 2 * HEADS * D_IN; o += blockDim.x) {
            int kind = o >> 8;
            int h = (o >> 6) & 3;
            int c = o & 63;
            const float* av = (kind ? att_dst : att_src) + h * 64;
            float s = 0.f;
#pragma unroll 8
            for (int j = 0; j < 64; j++) s += W[(size_t)c * HC + h * 64 + j] * av[j];
            if (kind) g_wad[h * 64 + c] = s;
            else      g_was[h * 64 + c] = s;
        }
    }
}

// ---------------------------------------------------------------------------
// 2. Count in-degrees (4 edges per thread)
// ---------------------------------------------------------------------------
__global__ void count_kernel(const void* __restrict__ ei, int E) {
    int e = (blockIdx.x * blockDim.x + threadIdx.x) * 4;
    if (e >= E) return;
    int is64 = g_is64;
    if (e + 3 < E) {
        int d[4];
        if (is64) {
            longlong2 p0 = *(const longlong2*)((const long long*)ei + (size_t)E + e);
            longlong2 p1 = *(const longlong2*)((const long long*)ei + (size_t)E + e + 2);
            d[0] = (int)p0.x; d[1] = (int)p0.y; d[2] = (int)p1.x; d[3] = (int)p1.y;
        } else {
            int4 p = *(const int4*)((const int*)ei + (size_t)E + e);
            d[0] = p.x; d[1] = p.y; d[2] = p.z; d[3] = p.w;
        }
#pragma unroll
        for (int k = 0; k < 4; k++) atomicAdd(&g_cnt[d[k]], 1);
    } else {
        for (int k = e; k < E; k++)
            atomicAdd(&g_cnt[(int)load_edge(ei, is64, (size_t)E + k)], 1);
    }
}

// ---------------------------------------------------------------------------
// 3a. Block-local exclusive scan
// ---------------------------------------------------------------------------
__global__ void scan1_kernel(int N) {
    int t = threadIdx.x;
    int i = blockIdx.x * SCAN_B + t;
    int lane = t & 31, wid = t >> 5;

    int v = (i < N) ? g_cnt[i] : 0;
    int x = v;
#pragma unroll
    for (int off = 1; off < 32; off <<= 1) {
        int u = __shfl_up_sync(0xffffffffu, x, off);
        if (lane >= off) x += u;
    }
    __shared__ int wsum[32];
    if (lane == 31) wsum[wid] = x;
    __syncthreads();
    if (wid == 0) {
        int y = wsum[lane];
#pragma unroll
        for (int off = 1; off < 32; off <<= 1) {
            int u = __shfl_up_sync(0xffffffffu, y, off);
            if (lane >= off) y += u;
        }
        wsum[lane] = y;
    }
    __syncthreads();
    int base = (wid > 0) ? wsum[wid - 1] : 0;
    int incl = base + x;
    if (i < N) g_off[i] = incl - v;
    if (t == SCAN_B - 1) g_bsum[blockIdx.x] = incl;
}

// ---------------------------------------------------------------------------
// 4. Attention scores + fp16 convert. 4 nodes/warp, 8-lane groups.
//    was/wad tables staged in smem once per block (2 KB, reused 128x).
// ---------------------------------------------------------------------------
__global__ void att_kernel(const float* __restrict__ x, int N) {
    __shared__ float sws[HEADS * D_IN];
    __shared__ float swd[HEADS * D_IN];
    int t = threadIdx.x;
    if (t < 256) {
        sws[t] = g_was[t];
        swd[t] = g_wad[t];
    }
    __syncthreads();

    int gw = (blockIdx.x * blockDim.x + t) >> 5;
    int lane = t & 31;
    int g = lane >> 3, l8 = lane & 7;
    int node = gw * 4 + g;
    if (node >= N) return;

    const float* xr = x + (size_t)node * D_IN + l8 * 8;
    float4 v0 = *(const float4*)xr;
    float4 v1 = *(const float4*)(xr + 4);

    __half2 h0 = __floats2half2_rn(v0.x, v0.y);
    __half2 h1 = __floats2half2_rn(v0.z, v0.w);
    __half2 h2 = __floats2half2_rn(v1.x, v1.y);
    __half2 h3 = __floats2half2_rn(v1.z, v1.w);
    uint4 pk = make_uint4(*(uint32_t*)&h0, *(uint32_t*)&h1, *(uint32_t*)&h2, *(uint32_t*)&h3);
    *(uint4*)(g_x16 + (size_t)node * D_IN + l8 * 8) = pk;

    float ps[4], pd[4];
#pragma unroll
    for (int h = 0; h < 4; h++) {
        const float* ws = sws + h * 64 + l8 * 8;
        const float* wd = swd + h * 64 + l8 * 8;
        float4 s0 = *(const float4*)ws, s1 = *(const float4*)(ws + 4);
        float4 d0 = *(const float4*)wd, d1 = *(const float4*)(wd + 4);
        ps[h] = v0.x * s0.x + v0.y * s0.y + v0.z * s0.z + v0.w * s0.w
              + v1.x * s1.x + v1.y * s1.y + v1.z * s1.z + v1.w * s1.w;
        pd[h] = v0.x * d0.x + v0.y * d0.y + v0.z * d0.z + v0.w * d0.w
              + v1.x * d1.x + v1.y * d1.y + v1.z * d1.z + v1.w * d1.w;
    }
#pragma unroll
    for (int off = 4; off > 0; off >>= 1) {
#pragma unroll
        for (int h = 0; h < 4; h++) {
            ps[h] += __shfl_xor_sync(0xffffffffu, ps[h], off, 8);
            pd[h] += __shfl_xor_sync(0xffffffffu, pd[h], off, 8);
        }
    }
    if (l8 == 0) {
        *(float4*)(g_asrc + node * HEADS) = make_float4(ps[0], ps[1], ps[2], ps[3]);
        *(float4*)(g_adst + node * HEADS) = make_float4(pd[0], pd[1], pd[2], pd[3]);
    }
}

// ---------------------------------------------------------------------------
// 3b/3c. Scan block sums + add bases
// ---------------------------------------------------------------------------
__global__ void scan2_kernel(int nb, int N, int E) {
    int t = threadIdx.x, lane = t & 31, wid = t >> 5;
    int v = (t < nb) ? g_bsum[t] : 0;
    int x = v;
#pragma unroll
    for (int off = 1; off < 32; off <<= 1) {
        int u = __shfl_up_sync(0xffffffffu, x, off);
        if (lane >= off) x += u;
    }
    __shared__ int ws[4];
    __shared__ int wpre[4];
    if (lane == 31) ws[wid] = x;
    __syncthreads();
    if (t == 0) {
        int s = 0;
#pragma unroll
        for (int k = 0; k < 4; k++) { wpre[k] = s; s += ws[k]; }
    }
    __syncthreads();
    int incl = wpre[wid] + x;
    if (t < nb) g_bpre[t] = incl - v;
    if (t == 0) g_off[N] = E;
}

__global__ void scan3_kernel(int N) {
    int i = blockIdx.x * SCAN_B + threadIdx.x;
    if (i < N) {
        int o = g_off[i] + g_bpre[blockIdx.x];
        g_off[i] = o;
        g_cur[i] = o;
    }
}

// ---------------------------------------------------------------------------
// 5. Scatter src ids into CSR slots (4 edges per thread)
// ---------------------------------------------------------------------------
__global__ void scatter_kernel(const void* __restrict__ ei, int E) {
    int e = (blockIdx.x * blockDim.x + threadIdx.x) * 4;
    if (e >= E) return;
    int is64 = g_is64;
    if (e + 3 < E) {
        int s[4], d[4];
        if (is64) {
            longlong2 ps0 = *(const longlong2*)((const long long*)ei + e);
            longlong2 ps1 = *(const longlong2*)((const long long*)ei + e + 2);
            longlong2 pd0 = *(const longlong2*)((const long long*)ei + (size_t)E + e);
            longlong2 pd1 = *(const longlong2*)((const long long*)ei + (size_t)E + e + 2);
            s[0] = (int)ps0.x; s[1] = (int)ps0.y; s[2] = (int)ps1.x; s[3] = (int)ps1.y;
            d[0] = (int)pd0.x; d[1] = (int)pd0.y; d[2] = (int)pd1.x; d[3] = (int)pd1.y;
        } else {
            int4 ps = *(const int4*)((const int*)ei + e);
            int4 pd = *(const int4*)((const int*)ei + (size_t)E + e);
            s[0] = ps.x; s[1] = ps.y; s[2] = ps.z; s[3] = ps.w;
            d[0] = pd.x; d[1] = pd.y; d[2] = pd.z; d[3] = pd.w;
        }
#pragma unroll
        for (int k = 0; k < 4; k++) {
            int pos = atomicAdd(&g_cur[d[k]], 1);
            g_srclist[pos] = s[k];
        }
    } else {
        for (int k = e; k < E; k++) {
            int s = (int)load_edge(ei, is64, k);
            int d = (int)load_edge(ei, is64, (size_t)E + k);
            int pos = atomicAdd(&g_cur[d], 1);
            g_srclist[pos] = s;
        }
    }
}

// ---------------------------------------------------------------------------
// 6. Aggregate in x-space (r8/r9 proven version).
// ---------------------------------------------------------------------------
__global__ void agg_kernel(int N) {
    __shared__ float4 swe[8][32];
    __shared__ int    ssid[8][32];
    int wl = threadIdx.x >> 5;
    int w = (blockIdx.x * blockDim.x + threadIdx.x) >> 5;
    int lane = threadIdx.x & 31;
    if (w >= N) return;

    __half2* arow = (__half2*)(g_agg + (size_t)w * HC);
    int beg = g_off[w];
    int end = g_off[w + 1];
    if (beg == end) {
        __half2 z = __floats2half2_rn(0.f, 0.f);
#pragma unroll
        for (int h = 0; h < 4; h++) arow[h * 32 + lane] = z;
        return;
    }

    float4 ad4 = *(const float4*)(g_adst + w * HEADS);
    float4 den4 = make_float4(0.f, 0.f, 0.f, 0.f);
    float acc[8];
#pragma unroll
    for (int k = 0; k < 8; k++) acc[k] = 0.f;

    for (int base = beg; base < end; base += 32) {
        int c = min(end - base, 32);
        if (lane < c) {
            int s = g_srclist[base + lane];
            float4 as = *(const float4*)(g_asrc + s * HEADS);
            float4 we;
            we.x = __expf(leaky(as.x + ad4.x));
            we.y = __expf(leaky(as.y + ad4.y));
            we.z = __expf(leaky(as.z + ad4.z));
            we.w = __expf(leaky(as.w + ad4.w));
            den4.x += we.x; den4.y += we.y; den4.z += we.z; den4.w += we.w;
            swe[wl][lane] = we;
            ssid[wl][lane] = s;
        }
        __syncwarp();

        uint32_t x0 = *(const uint32_t*)(g_x16 + (size_t)ssid[wl][0] * D_IN + lane * 2);
        for (int j = 0; j < c; j++) {
            uint32_t x1 = 0;
            if (j + 1 < c)
                x1 = *(const uint32_t*)(g_x16 + (size_t)ssid[wl][j + 1] * D_IN + lane * 2);
            float4 we = swe[wl][j];
            float2 xv = __half22float2(*(__half2*)&x0);
            acc[0] += we.x * xv.x; acc[1] += we.x * xv.y;
            acc[2] += we.y * xv.x; acc[3] += we.y * xv.y;
            acc[4] += we.z * xv.x; acc[5] += we.z * xv.y;
            acc[6] += we.w * xv.x; acc[7] += we.w * xv.y;
            x0 = x1;
        }
        __syncwarp();
    }

#pragma unroll
    for (int off = 16; off > 0; off >>= 1) {
        den4.x += __shfl_xor_sync(0xffffffffu, den4.x, off);
        den4.y += __shfl_xor_sync(0xffffffffu, den4.y, off);
        den4.z += __shfl_xor_sync(0xffffffffu, den4.z, off);
        den4.w += __shfl_xor_sync(0xffffffffu, den4.w, off);
    }
    float ix = 1.f / (den4.x + 1e-16f);
    float iy = 1.f / (den4.y + 1e-16f);
    float iz = 1.f / (den4.z + 1e-16f);
    float iw = 1.f / (den4.w + 1e-16f);
    arow[0 * 32 + lane] = __floats2half2_rn(acc[0] * ix, acc[1] * ix);
    arow[1 * 32 + lane] = __floats2half2_rn(acc[2] * iy, acc[3] * iy);
    arow[2 * 32 + lane] = __floats2half2_rn(acc[4] * iz, acc[5] * iz);
    arow[3 * 32 + lane] = __floats2half2_rn(acc[6] * iw, acc[7] * iw);
}

// ---------------------------------------------------------------------------
// 7. Output GEMM with ldmatrix fragment loads (r9 proven version).
// ---------------------------------------------------------------------------
__global__ void __launch_bounds__(256, 2)
gemm_out_kernel(const float* __restrict__ W, const float* __restrict__ bias,
                float* __restrict__ out, int n) {
    extern __shared__ uint32_t sm[];
    uint32_t* sA = sm;                       // 64 rows x SAP uint32
    __half*  sBh = (__half*)(sm + 64 * SAP); // 64 k-rows x SWN halves

    int t = threadIdx.x;
    int lane = t & 31;
    int wid = t >> 5;
    int wm = wid >> 2;
    int wn = wid & 3;          // head
    int row0 = blockIdx.x * 64;

#pragma unroll
    for (int i = 0; i < 8; i++) {
        int idx = t + i * 256;
        int r = idx >> 5, c4 = idx & 31;
        uint4 v = make_uint4(0, 0, 0, 0);
        if (row0 + r < n) v = *(const uint4*)(g_agg + (size_t)(row0 + r) * HC + c4 * 8);
        uint32_t* p = sA + r * SAP + c4 * 4;
        p[0] = v.x; p[1] = v.y; p[2] = v.z; p[3] = v.w;
    }

#pragma unroll
    for (int i = 0; i < 16; i++) {
        int idx4 = t + i * 256;
        int k = idx4 >> 6, c = (idx4 & 63) * 4;
        float4 v = *(const float4*)(W + (size_t)k * HC + c);
        __half2* q = (__half2*)(sBh + k * SWN + c);
        q[0] = __floats2half2_rn(v.x, v.y);
        q[1] = __floats2half2_rn(v.z, v.w);
    }
    __syncthreads();

    uint32_t smem_base = (uint32_t)__cvta_generic_to_shared(sm);
    uint32_t sB_base = smem_base + 64 * SAP * 4;

    int l8 = lane & 7;
    int lrow8 = (lane >> 3) & 1;
    int lk8 = (lane >> 4) & 1;

    uint32_t aAddr[2];
#pragma unroll
    for (int mt = 0; mt < 2; mt++) {
        int r = wm * 32 + mt * 16 + l8 + lrow8 * 8;
        aAddr[mt] = smem_base + r * (SAP * 4) + (wn * 64 + lk8 * 8) * 2;
    }
    uint32_t bAddr[4];
#pragma unroll
    for (int ntp = 0; ntp < 4; ntp++) {
        int krow = l8 + lrow8 * 8;
        bAddr[ntp] = sB_base + krow * (SWN * 2) + (wn * 64 + ntp * 16 + lk8 * 8) * 2;
    }

    float acc[2][8][4];
#pragma unroll
    for (int mt = 0; mt < 2; mt++)
#pragma unroll
        for (int nt = 0; nt < 8; nt++)
#pragma unroll
            for (int k = 0; k < 4; k++) acc[mt][nt][k] = 0.f;

#pragma unroll
    for (int kc = 0; kc < 4; kc++) {
        uint32_t a[2][4];
#pragma unroll
        for (int mt = 0; mt < 2; mt++) {
            asm volatile(
                "ldmatrix.sync.aligned.m8n8.x4.shared.b16 {%0,%1,%2,%3}, [%4];"
                : "=r"(a[mt][0]), "=r"(a[mt][1]), "=r"(a[mt][2]), "=r"(a[mt][3])
                : "r"(aAddr[mt] + kc * 32));
        }
        uint32_t b[4][4];
#pragma unroll
        for (int ntp = 0; ntp < 4; ntp++) {
            asm volatile(
                "ldmatrix.sync.aligned.m8n8.x4.trans.shared.b16 {%0,%1,%2,%3}, [%4];"
                : "=r"(b[ntp][0]), "=r"(b[ntp][1]), "=r"(b[ntp][2]), "=r"(b[ntp][3])
                : "r"(bAddr[ntp] + kc * 16 * (SWN * 2)));
        }
#pragma unroll
        for (int mt = 0; mt < 2; mt++)
#pragma unroll
            for (int nt = 0; nt < 8; nt++) {
                float* c = acc[mt][nt];
                uint32_t b0 = b[nt >> 1][(nt & 1) * 2 + 0];
                uint32_t b1 = b[nt >> 1][(nt & 1) * 2 + 1];
                asm volatile(
                    "mma.sync.aligned.m16n8k16.row.col.f32.f16.f16.f32 "
                    "{%0,%1,%2,%3}, {%4,%5,%6,%7}, {%8,%9}, {%0,%1,%2,%3};"
                    : "+f"(c[0]), "+f"(c[1]), "+f"(c[2]), "+f"(c[3])
                    : "r"(a[mt][0]), "r"(a[mt][1]), "r"(a[mt][2]), "r"(a[mt][3]),
                      "r"(b0), "r"(b1));
            }
    }

    int qr = lane >> 2;
    int ql = lane & 3;
#pragma unroll
    for (int mt = 0; mt < 2; mt++) {
        int r_lo = row0 + wm * 32 + mt * 16 + qr;
#pragma unroll
        for (int nt = 0; nt < 8; nt++) {
            int col = wn * 64 + nt * 8 + 2 * ql;
            float2 bb = *(const float2*)(bias + col);
            const float* c = acc[mt][nt];
            if (r_lo < n)
                *(float2*)(out + (size_t)r_lo * HC + col) = make_float2(c[0] + bb.x, c[1] + bb.y);
            if (r_lo + 8 < n)
                *(float2*)(out + (size_t)(r_lo + 8) * HC + col) = make_float2(c[2] + bb.x, c[3] + bb.y);
        }
    }
}

// ---------------------------------------------------------------------------
// Launch.  att_kernel is the 4th launch (ncu profiles launch #4).
// ---------------------------------------------------------------------------
extern "C" void kernel_launch(void* const* d_in, const int* in_sizes, int n_in,
                              void* d_out, int out_size) {
    const float* x        = (const float*)d_in[0];
    const void*  ei       = (const void*)d_in[1];
    const float* W        = (const float*)d_in[2];
    const float* att_src  = (const float*)d_in[3];
    const float* att_dst  = (const float*)d_in[4];
    const float* bias     = (const float*)d_in[5];
    float* out = (float*)d_out;

    int N = in_sizes[0] / D_IN;
    int E = in_sizes[1] / 2;

    init_kernel<<<(N + 255) / 256, 256>>>(ei, W, att_src, att_dst, N);  // 1
    count_kernel<<<(E / 4 + 256) / 256, 256>>>(ei, E);                  // 2

    int nb = (N + SCAN_B - 1) / SCAN_B;
    scan1_kernel<<<nb, SCAN_B>>>(N);                                    // 3

    int att_warps = (N + 3) / 4;
    att_kernel<<<(att_warps * 32 + 255) / 256, 256>>>(x, N);            // 4 (profiled)

    scan2_kernel<<<1, 128>>>(nb, N, E);                                 // 5
    scan3_kernel<<<nb, SCAN_B>>>(N);                                    // 6
    scatter_kernel<<<(E / 4 + 256) / 256, 256>>>(ei, E);                // 7

    long long agg_threads = (long long)N * 32;
    agg_kernel<<<(int)((agg_threads + 255) / 256), 256>>>(N);           // 8

    size_t smem = (size_t)64 * SAP * 4 + (size_t)64 * SWN * 2;          // 66 KB
    cudaFuncSetAttribute(gemm_out_kernel, cudaFuncAttributeMaxDynamicSharedMemorySize, (int)smem);
    gemm_out_kernel<<<(N + 63) / 64, 256, smem>>>(W, bias, out, N);     // 9
}

// round 12
// speedup vs baseline: 1.3320x; 1.0288x over previous
#include <cuda_runtime.h>
#include <cuda_fp16.h>
#include <math.h>
#include <float.h>
#include <stdint.h>

// Problem constants (GAT_38585986187787)
#define MAX_NODES 100000
#define MAX_EDGES 1600000
#define D_IN 64
#define HEADS 4
#define HC 256   // HEADS * C_OUT
#define SCAN_B 1024
#define MAX_SCAN_BLOCKS 128

#define SAP 132   // agg smem row stride (uint32): 528B/row -> 4-bank row spacing
#define SWN 264   // W smem row stride (halves):  528B/row -> 4-bank row spacing

// ---------------------------------------------------------------------------
// Device scratch
// ---------------------------------------------------------------------------
__device__ __half g_x16[(size_t)MAX_NODES * D_IN];  // 12.8 MB  x in fp16 (L2-resident)
__device__ __half g_agg[(size_t)MAX_NODES * HC];    // 51.2 MB  normalized weighted sums
__device__ float g_asrc[MAX_NODES * HEADS];
__device__ float g_adst[MAX_NODES * HEADS];
__device__ float g_was[HEADS * D_IN];               // W_h @ att_src_h
__device__ float g_wad[HEADS * D_IN];               // W_h @ att_dst_h
__device__ int   g_cnt[MAX_NODES];                  // ZERO invariant outside a run
__device__ int   g_off[MAX_NODES + 1];
__device__ int   g_cur[MAX_NODES];
__device__ int   g_srclist[MAX_EDGES];
__device__ int   g_bsum[MAX_SCAN_BLOCKS];
__device__ int   g_is64;

__device__ __forceinline__ long long load_edge(const void* ei, int is64, size_t idx) {
    if (is64) return ((const long long*)ei)[idx];
    return (long long)(((const int*)ei)[idx]);
}

__device__ __forceinline__ float leaky(float v) {
    return (v >= 0.f) ? v : 0.2f * v;
}

// ---------------------------------------------------------------------------
// 1. Init (ONE block): detect dtype + projected attention tables.
//    was[h][c] = sum_j W[c, h*64+j] * att_src[h][j]   (exact fp32)
// ---------------------------------------------------------------------------
__global__ void init_kernel(const void* ei, const float* __restrict__ W,
                            const float* __restrict__ att_src,
                            const float* __restrict__ att_dst) {
    if (threadIdx.x == 0) {
        const unsigned long long* p = (const unsigned long long*)ei;
        bool ok = true;
#pragma unroll
        for (int i = 0; i < 16; i++) ok = ok && (p[i] < (unsigned long long)MAX_NODES);
        g_is64 = ok ? 1 : 0;
    }
    for (int o = threadIdx.x; o < 2 * HEADS * D_IN; o += blockDim.x) {
        int kind = o >> 8;
        int h = (o >> 6) & 3;
        int c = o & 63;
        const float* av = (kind ? att_dst : att_src) + h * 64;
        float s = 0.f;
#pragma unroll 8
        for (int j = 0; j < 64; j++) s += W[(size_t)c * HC + h * 64 + j] * av[j];
        if (kind) g_wad[h * 64 + c] = s;
        else      g_was[h * 64 + c] = s;
    }
}

// ---------------------------------------------------------------------------
// 2. Count in-degrees (4 edges per thread).  g_cnt is zero on entry
//    (module init on first call; reset by scan23 on later replays).
// ---------------------------------------------------------------------------
__global__ void count_kernel(const void* __restrict__ ei, int E) {
    int e = (blockIdx.x * blockDim.x + threadIdx.x) * 4;
    if (e >= E) return;
    int is64 = g_is64;
    if (e + 3 < E) {
        int d[4];
        if (is64) {
            longlong2 p0 = *(const longlong2*)((const long long*)ei + (size_t)E + e);
            longlong2 p1 = *(const longlong2*)((const long long*)ei + (size_t)E + e + 2);
            d[0] = (int)p0.x; d[1] = (int)p0.y; d[2] = (int)p1.x; d[3] = (int)p1.y;
        } else {
            int4 p = *(const int4*)((const int*)ei + (size_t)E + e);
            d[0] = p.x; d[1] = p.y; d[2] = p.z; d[3] = p.w;
        }
#pragma unroll
        for (int k = 0; k < 4; k++) atomicAdd(&g_cnt[d[k]], 1);
    } else {
        for (int k = e; k < E; k++)
            atomicAdd(&g_cnt[(int)load_edge(ei, is64, (size_t)E + k)], 1);
    }
}

// ---------------------------------------------------------------------------
// 3a. Block-local exclusive scan -> g_off (local), block sums -> g_bsum
// ---------------------------------------------------------------------------
__global__ void scan1_kernel(int N) {
    int t = threadIdx.x;
    int i = blockIdx.x * SCAN_B + t;
    int lane = t & 31, wid = t >> 5;

    int v = (i < N) ? g_cnt[i] : 0;
    int x = v;
#pragma unroll
    for (int off = 1; off < 32; off <<= 1) {
        int u = __shfl_up_sync(0xffffffffu, x, off);
        if (lane >= off) x += u;
    }
    __shared__ int wsum[32];
    if (lane == 31) wsum[wid] = x;
    __syncthreads();
    if (wid == 0) {
        int y = wsum[lane];
#pragma unroll
        for (int off = 1; off < 32; off <<= 1) {
            int u = __shfl_up_sync(0xffffffffu, y, off);
            if (lane >= off) y += u;
        }
        wsum[lane] = y;
    }
    __syncthreads();
    int base = (wid > 0) ? wsum[wid - 1] : 0;
    int incl = base + x;
    if (i < N) g_off[i] = incl - v;
    if (t == SCAN_B - 1) g_bsum[blockIdx.x] = incl;
}

// ---------------------------------------------------------------------------
// 4. Attention scores + fp16 convert. Grid-stride, 4 nodes/warp/iter.
//    Lane's 32-float table slice lives in REGISTERS (reused ~24 nodes).
// ---------------------------------------------------------------------------
__global__ void att_kernel(const float* __restrict__ x, int N) {
    int t = threadIdx.x;
    int lane = t & 31;
    int g = lane >> 3, l8 = lane & 7;

    // Register-resident table slices for this lane's channel group
    float4 ws0[4], ws1[4], wd0[4], wd1[4];
#pragma unroll
    for (int h = 0; h < 4; h++) {
        const float* ws = g_was + h * 64 + l8 * 8;
        const float* wd = g_wad + h * 64 + l8 * 8;
        ws0[h] = *(const float4*)ws; ws1[h] = *(const float4*)(ws + 4);
        wd0[h] = *(const float4*)wd; wd1[h] = *(const float4*)(wd + 4);
    }

    int warp0 = (blockIdx.x * blockDim.x + t) >> 5;
    int nwarps = (gridDim.x * blockDim.x) >> 5;

    for (int node = warp0 * 4 + g; node < N; node += nwarps * 4) {
        const float* xr = x + (size_t)node * D_IN + l8 * 8;
        float4 v0 = *(const float4*)xr;
        float4 v1 = *(const float4*)(xr + 4);

        __half2 h0 = __floats2half2_rn(v0.x, v0.y);
        __half2 h1 = __floats2half2_rn(v0.z, v0.w);
        __half2 h2 = __floats2half2_rn(v1.x, v1.y);
        __half2 h3 = __floats2half2_rn(v1.z, v1.w);
        uint4 pk = make_uint4(*(uint32_t*)&h0, *(uint32_t*)&h1,
                              *(uint32_t*)&h2, *(uint32_t*)&h3);
        *(uint4*)(g_x16 + (size_t)node * D_IN + l8 * 8) = pk;

        float ps[4], pd[4];
#pragma unroll
        for (int h = 0; h < 4; h++) {
            ps[h] = v0.x * ws0[h].x + v0.y * ws0[h].y + v0.z * ws0[h].z + v0.w * ws0[h].w
                  + v1.x * ws1[h].x + v1.y * ws1[h].y + v1.z * ws1[h].z + v1.w * ws1[h].w;
            pd[h] = v0.x * wd0[h].x + v0.y * wd0[h].y + v0.z * wd0[h].z + v0.w * wd0[h].w
                  + v1.x * wd1[h].x + v1.y * wd1[h].y + v1.z * wd1[h].z + v1.w * wd1[h].w;
        }
#pragma unroll
        for (int off = 4; off > 0; off >>= 1) {
#pragma unroll
            for (int h = 0; h < 4; h++) {
                ps[h] += __shfl_xor_sync(0xffffffffu, ps[h], off, 8);
                pd[h] += __shfl_xor_sync(0xffffffffu, pd[h], off, 8);
            }
        }
        if (l8 == 0) {
            *(float4*)(g_asrc + node * HEADS) = make_float4(ps[0], ps[1], ps[2], ps[3]);
            *(float4*)(g_adst + node * HEADS) = make_float4(pd[0], pd[1], pd[2], pd[3]);
        }
    }
}

// ---------------------------------------------------------------------------
// 3b+3c merged: each block reduces its prefix of g_bsum itself, adds base,
//    emits cursors, resets g_cnt (restores zero invariant for next replay).
// ---------------------------------------------------------------------------
__global__ void scan23_kernel(int nb, int N, int E) {
    __shared__ int spart[4];
    int t = threadIdx.x;
    int lane = t & 31, wid = t >> 5;

    // Reduce g_bsum[0 .. blockIdx.x) over first 128 threads
    int v = (t < 128 && t < blockIdx.x) ? g_bsum[t] : 0;
    if (t < 128) {
#pragma unroll
        for (int off = 16; off > 0; off >>= 1)
            v += __shfl_xor_sync(0xffffffffu, v, off);
        if (lane == 0) spart[wid] = v;
    }
    __syncthreads();
    int base = spart[0] + spart[1] + spart[2] + spart[3];

    int i = blockIdx.x * SCAN_B + t;
    if (i < N) {
        int o = g_off[i] + base;
        g_off[i] = o;
        g_cur[i] = o;
        g_cnt[i] = 0;          // restore invariant for next graph replay
    }
    if (blockIdx.x == 0 && t == 0) g_off[N] = E;
}

// ---------------------------------------------------------------------------
// 5. Scatter src ids into CSR slots (4 edges per thread)
// ---------------------------------------------------------------------------
__global__ void scatter_kernel(const void* __restrict__ ei, int E) {
    int e = (blockIdx.x * blockDim.x + threadIdx.x) * 4;
    if (e >= E) return;
    int is64 = g_is64;
    if (e + 3 < E) {
        int s[4], d[4];
        if (is64) {
            longlong2 ps0 = *(const longlong2*)((const long long*)ei + e);
            longlong2 ps1 = *(const longlong2*)((const long long*)ei + e + 2);
            longlong2 pd0 = *(const longlong2*)((const long long*)ei + (size_t)E + e);
            longlong2 pd1 = *(const longlong2*)((const long long*)ei + (size_t)E + e + 2);
            s[0] = (int)ps0.x; s[1] = (int)ps0.y; s[2] = (int)ps1.x; s[3] = (int)ps1.y;
            d[0] = (int)pd0.x; d[1] = (int)pd0.y; d[2] = (int)pd1.x; d[3] = (int)pd1.y;
        } else {
            int4 ps = *(const int4*)((const int*)ei + e);
            int4 pd = *(const int4*)((const int*)ei + (size_t)E + e);
            s[0] = ps.x; s[1] = ps.y; s[2] = ps.z; s[3] = ps.w;
            d[0] = pd.x; d[1] = pd.y; d[2] = pd.z; d[3] = pd.w;
        }
#pragma unroll
        for (int k = 0; k < 4; k++) {
            int pos = atomicAdd(&g_cur[d[k]], 1);
            g_srclist[pos] = s[k];
        }
    } else {
        for (int k = e; k < E; k++) {
            int s = (int)load_edge(ei, is64, k);
            int d = (int)load_edge(ei, is64, (size_t)E + k);
            int pos = atomicAdd(&g_cur[d], 1);
            g_srclist[pos] = s;
        }
    }
}

// ---------------------------------------------------------------------------
// 6. Aggregate in x-space (r8/r9 proven version).
// ---------------------------------------------------------------------------
__global__ void agg_kernel(int N) {
    __shared__ float4 swe[8][32];
    __shared__ int    ssid[8][32];
    int wl = threadIdx.x >> 5;
    int w = (blockIdx.x * blockDim.x + threadIdx.x) >> 5;
    int lane = threadIdx.x & 31;
    if (w >= N) return;

    __half2* arow = (__half2*)(g_agg + (size_t)w * HC);
    int beg = g_off[w];
    int end = g_off[w + 1];
    if (beg == end) {
        __half2 z = __floats2half2_rn(0.f, 0.f);
#pragma unroll
        for (int h = 0; h < 4; h++) arow[h * 32 + lane] = z;
        return;
    }

    float4 ad4 = *(const float4*)(g_adst + w * HEADS);
    float4 den4 = make_float4(0.f, 0.f, 0.f, 0.f);
    float acc[8];
#pragma unroll
    for (int k = 0; k < 8; k++) acc[k] = 0.f;

    for (int base = beg; base < end; base += 32) {
        int c = min(end - base, 32);
        if (lane < c) {
            int s = g_srclist[base + lane];
            float4 as = *(const float4*)(g_asrc + s * HEADS);
            float4 we;
            we.x = __expf(leaky(as.x + ad4.x));
            we.y = __expf(leaky(as.y + ad4.y));
            we.z = __expf(leaky(as.z + ad4.z));
            we.w = __expf(leaky(as.w + ad4.w));
            den4.x += we.x; den4.y += we.y; den4.z += we.z; den4.w += we.w;
            swe[wl][lane] = we;
            ssid[wl][lane] = s;
        }
        __syncwarp();

        uint32_t x0 = *(const uint32_t*)(g_x16 + (size_t)ssid[wl][0] * D_IN + lane * 2);
        for (int j = 0; j < c; j++) {
            uint32_t x1 = 0;
            if (j + 1 < c)
                x1 = *(const uint32_t*)(g_x16 + (size_t)ssid[wl][j + 1] * D_IN + lane * 2);
            float4 we = swe[wl][j];
            float2 xv = __half22float2(*(__half2*)&x0);
            acc[0] += we.x * xv.x; acc[1] += we.x * xv.y;
            acc[2] += we.y * xv.x; acc[3] += we.y * xv.y;
            acc[4] += we.z * xv.x; acc[5] += we.z * xv.y;
            acc[6] += we.w * xv.x; acc[7] += we.w * xv.y;
            x0 = x1;
        }
        __syncwarp();
    }

#pragma unroll
    for (int off = 16; off > 0; off >>= 1) {
        den4.x += __shfl_xor_sync(0xffffffffu, den4.x, off);
        den4.y += __shfl_xor_sync(0xffffffffu, den4.y, off);
        den4.z += __shfl_xor_sync(0xffffffffu, den4.z, off);
        den4.w += __shfl_xor_sync(0xffffffffu, den4.w, off);
    }
    float ix = 1.f / (den4.x + 1e-16f);
    float iy = 1.f / (den4.y + 1e-16f);
    float iz = 1.f / (den4.z + 1e-16f);
    float iw = 1.f / (den4.w + 1e-16f);
    arow[0 * 32 + lane] = __floats2half2_rn(acc[0] * ix, acc[1] * ix);
    arow[1 * 32 + lane] = __floats2half2_rn(acc[2] * iy, acc[3] * iy);
    arow[2 * 32 + lane] = __floats2half2_rn(acc[4] * iz, acc[5] * iz);
    arow[3 * 32 + lane] = __floats2half2_rn(acc[6] * iw, acc[7] * iw);
}

// ---------------------------------------------------------------------------
// 7. Output GEMM with ldmatrix fragment loads (r9 proven version).
// ---------------------------------------------------------------------------
__global__ void __launch_bounds__(256, 2)
gemm_out_kernel(const float* __restrict__ W, const float* __restrict__ bias,
                float* __restrict__ out, int n) {
    extern __shared__ uint32_t sm[];
    uint32_t* sA = sm;                       // 64 rows x SAP uint32
    __half*  sBh = (__half*)(sm + 64 * SAP); // 64 k-rows x SWN halves

    int t = threadIdx.x;
    int lane = t & 31;
    int wid = t >> 5;
    int wm = wid >> 2;
    int wn = wid & 3;          // head
    int row0 = blockIdx.x * 64;

#pragma unroll
    for (int i = 0; i < 8; i++) {
        int idx = t + i * 256;
        int r = idx >> 5, c4 = idx & 31;
        uint4 v = make_uint4(0, 0, 0, 0);
        if (row0 + r < n) v = *(const uint4*)(g_agg + (size_t)(row0 + r) * HC + c4 * 8);
        uint32_t* p = sA + r * SAP + c4 * 4;
        p[0] = v.x; p[1] = v.y; p[2] = v.z; p[3] = v.w;
    }

#pragma unroll
    for (int i = 0; i < 16; i++) {
        int idx4 = t + i * 256;
        int k = idx4 >> 6, c = (idx4 & 63) * 4;
        float4 v = *(const float4*)(W + (size_t)k * HC + c);
        __half2* q = (__half2*)(sBh + k * SWN + c);
        q[0] = __floats2half2_rn(v.x, v.y);
        q[1] = __floats2half2_rn(v.z, v.w);
    }
    __syncthreads();

    uint32_t smem_base = (uint32_t)__cvta_generic_to_shared(sm);
    uint32_t sB_base = smem_base + 64 * SAP * 4;

    int l8 = lane & 7;
    int lrow8 = (lane >> 3) & 1;
    int lk8 = (lane >> 4) & 1;

    uint32_t aAddr[2];
#pragma unroll
    for (int mt = 0; mt < 2; mt++) {
        int r = wm * 32 + mt * 16 + l8 + lrow8 * 8;
        aAddr[mt] = smem_base + r * (SAP * 4) + (wn * 64 + lk8 * 8) * 2;
    }
    uint32_t bAddr[4];
#pragma unroll
    for (int ntp = 0; ntp < 4; ntp++) {
        int krow = l8 + lrow8 * 8;
        bAddr[ntp] = sB_base + krow * (SWN * 2) + (wn * 64 + ntp * 16 + lk8 * 8) * 2;
    }

    float acc[2][8][4];
#pragma unroll
    for (int mt = 0; mt < 2; mt++)
#pragma unroll
        for (int nt = 0; nt < 8; nt++)
#pragma unroll
            for (int k = 0; k < 4; k++) acc[mt][nt][k] = 0.f;

#pragma unroll
    for (int kc = 0; kc < 4; kc++) {
        uint32_t a[2][4];
#pragma unroll
        for (int mt = 0; mt < 2; mt++) {
            asm volatile(
                "ldmatrix.sync.aligned.m8n8.x4.shared.b16 {%0,%1,%2,%3}, [%4];"
                : "=r"(a[mt][0]), "=r"(a[mt][1]), "=r"(a[mt][2]), "=r"(a[mt][3])
                : "r"(aAddr[mt] + kc * 32));
        }
        uint32_t b[4][4];
#pragma unroll
        for (int ntp = 0; ntp < 4; ntp++) {
            asm volatile(
                "ldmatrix.sync.aligned.m8n8.x4.trans.shared.b16 {%0,%1,%2,%3}, [%4];"
                : "=r"(b[ntp][0]), "=r"(b[ntp][1]), "=r"(b[ntp][2]), "=r"(b[ntp][3])
                : "r"(bAddr[ntp] + kc * 16 * (SWN * 2)));
        }
#pragma unroll
        for (int mt = 0; mt < 2; mt++)
#pragma unroll
            for (int nt = 0; nt < 8; nt++) {
                float* c = acc[mt][nt];
                uint32_t b0 = b[nt >> 1][(nt & 1) * 2 + 0];
                uint32_t b1 = b[nt >> 1][(nt & 1) * 2 + 1];
                asm volatile(
                    "mma.sync.aligned.m16n8k16.row.col.f32.f16.f16.f32 "
                    "{%0,%1,%2,%3}, {%4,%5,%6,%7}, {%8,%9}, {%0,%1,%2,%3};"
                    : "+f"(c[0]), "+f"(c[1]), "+f"(c[2]), "+f"(c[3])
                    : "r"(a[mt][0]), "r"(a[mt][1]), "r"(a[mt][2]), "r"(a[mt][3]),
                      "r"(b0), "r"(b1));
            }
    }

    int qr = lane >> 2;
    int ql = lane & 3;
#pragma unroll
    for (int mt = 0; mt < 2; mt++) {
        int r_lo = row0 + wm * 32 + mt * 16 + qr;
#pragma unroll
        for (int nt = 0; nt < 8; nt++) {
            int col = wn * 64 + nt * 8 + 2 * ql;
            float2 bb = *(const float2*)(bias + col);
            const float* c = acc[mt][nt];
            if (r_lo < n)
                *(float2*)(out + (size_t)r_lo * HC + col) = make_float2(c[0] + bb.x, c[1] + bb.y);
            if (r_lo + 8 < n)
                *(float2*)(out + (size_t)(r_lo + 8) * HC + col) = make_float2(c[2] + bb.x, c[3] + bb.y);
        }
    }
}

// ---------------------------------------------------------------------------
// Launch.  att_kernel is the 4th launch (ncu profiles launch #4).
// ---------------------------------------------------------------------------
extern "C" void kernel_launch(void* const* d_in, const int* in_sizes, int n_in,
                              void* d_out, int out_size) {
    const float* x        = (const float*)d_in[0];
    const void*  ei       = (const void*)d_in[1];
    const float* W        = (const float*)d_in[2];
    const float* att_src  = (const float*)d_in[3];
    const float* att_dst  = (const float*)d_in[4];
    const float* bias     = (const float*)d_in[5];
    float* out = (float*)d_out;

    int N = in_sizes[0] / D_IN;
    int E = in_sizes[1] / 2;

    init_kernel<<<1, 256>>>(ei, W, att_src, att_dst);                   // 1
    count_kernel<<<(E / 4 + 256) / 256, 256>>>(ei, E);                  // 2

    int nb = (N + SCAN_B - 1) / SCAN_B;   // 98 <= 128
    scan1_kernel<<<nb, SCAN_B>>>(N);                                    // 3

    att_kernel<<<512, 256>>>(x, N);                                     // 4 (profiled)

    scan23_kernel<<<nb, SCAN_B>>>(nb, N, E);                            // 5
    scatter_kernel<<<(E / 4 + 256) / 256, 256>>>(ei, E);                // 6

    long long agg_threads = (long long)N * 32;
    agg_kernel<<<(int)((agg_threads + 255) / 256), 256>>>(N);           // 7

    size_t smem = (size_t)64 * SAP * 4 + (size_t)64 * SWN * 2;          // 66 KB
    cudaFuncSetAttribute(gemm_out_kernel, cudaFuncAttributeMaxDynamicSharedMemorySize, (int)smem);
    gemm_out_kernel<<<(N + 63) / 64, 256, smem>>>(W, bias, out, N);     // 8
}

// round 13
// speedup vs baseline: 1.3806x; 1.0365x over previous
#include <cuda_runtime.h>
#include <cuda_fp16.h>
#include <math.h>
#include <float.h>
#include <stdint.h>

// Problem constants (GAT_38585986187787)
#define MAX_NODES 100000
#define MAX_EDGES 1600000
#define D_IN 64
#define HEADS 4
#define HC 256   // HEADS * C_OUT
#define SCAN_B 1024
#define MAX_SCAN_BLOCKS 128

#define SAP 132   // agg smem row stride (uint32): 528B/row -> 4-bank row spacing
#define SWN 264   // W smem row stride (halves):  528B/row -> 4-bank row spacing

// ---------------------------------------------------------------------------
// Device scratch
// ---------------------------------------------------------------------------
__device__ __half g_x16[(size_t)MAX_NODES * D_IN];  // 12.8 MB  x in fp16 (L2-resident)
__device__ __half g_agg[(size_t)MAX_NODES * HC];    // 51.2 MB  normalized weighted sums
__device__ float g_asrc[MAX_NODES * HEADS];
__device__ float g_adst[MAX_NODES * HEADS];
__device__ float g_was[HEADS * D_IN];               // W_h @ att_src_h
__device__ float g_wad[HEADS * D_IN];               // W_h @ att_dst_h
__device__ int   g_cnt[MAX_NODES];                  // ZERO invariant outside a run
__device__ int   g_off[MAX_NODES + 1];
__device__ int   g_cur[MAX_NODES];
__device__ int   g_srclist[MAX_EDGES];
__device__ int   g_bsum[MAX_SCAN_BLOCKS];
__device__ int   g_is64;

__device__ __forceinline__ long long load_edge(const void* ei, int is64, size_t idx) {
    if (is64) return ((const long long*)ei)[idx];
    return (long long)(((const int*)ei)[idx]);
}

__device__ __forceinline__ float leaky(float v) {
    return (v >= 0.f) ? v : 0.2f * v;
}

// ---------------------------------------------------------------------------
// 1. Init (ONE block): detect dtype + projected attention tables.
// ---------------------------------------------------------------------------
__global__ void init_kernel(const void* ei, const float* __restrict__ W,
                            const float* __restrict__ att_src,
                            const float* __restrict__ att_dst) {
    if (threadIdx.x == 0) {
        const unsigned long long* p = (const unsigned long long*)ei;
        bool ok = true;
#pragma unroll
        for (int i = 0; i < 16; i++) ok = ok && (p[i] < (unsigned long long)MAX_NODES);
        g_is64 = ok ? 1 : 0;
    }
    for (int o = threadIdx.x; o < 2 * HEADS * D_IN; o += blockDim.x) {
        int kind = o >> 8;
        int h = (o >> 6) & 3;
        int c = o & 63;
        const float* av = (kind ? att_dst : att_src) + h * 64;
        float s = 0.f;
#pragma unroll 8
        for (int j = 0; j < 64; j++) s += W[(size_t)c * HC + h * 64 + j] * av[j];
        if (kind) g_wad[h * 64 + c] = s;
        else      g_was[h * 64 + c] = s;
    }
}

// ---------------------------------------------------------------------------
// 2. Count in-degrees (4 edges per thread); g_cnt zero on entry.
// ---------------------------------------------------------------------------
__global__ void count_kernel(const void* __restrict__ ei, int E) {
    int e = (blockIdx.x * blockDim.x + threadIdx.x) * 4;
    if (e >= E) return;
    int is64 = g_is64;
    if (e + 3 < E) {
        int d[4];
        if (is64) {
            longlong2 p0 = *(const longlong2*)((const long long*)ei + (size_t)E + e);
            longlong2 p1 = *(const longlong2*)((const long long*)ei + (size_t)E + e + 2);
            d[0] = (int)p0.x; d[1] = (int)p0.y; d[2] = (int)p1.x; d[3] = (int)p1.y;
        } else {
            int4 p = *(const int4*)((const int*)ei + (size_t)E + e);
            d[0] = p.x; d[1] = p.y; d[2] = p.z; d[3] = p.w;
        }
#pragma unroll
        for (int k = 0; k < 4; k++) atomicAdd(&g_cnt[d[k]], 1);
    } else {
        for (int k = e; k < E; k++)
            atomicAdd(&g_cnt[(int)load_edge(ei, is64, (size_t)E + k)], 1);
    }
}

// ---------------------------------------------------------------------------
// 3a. Block-local exclusive scan -> g_off (local), block sums -> g_bsum
// ---------------------------------------------------------------------------
__global__ void scan1_kernel(int N) {
    int t = threadIdx.x;
    int i = blockIdx.x * SCAN_B + t;
    int lane = t & 31, wid = t >> 5;

    int v = (i < N) ? g_cnt[i] : 0;
    int x = v;
#pragma unroll
    for (int off = 1; off < 32; off <<= 1) {
        int u = __shfl_up_sync(0xffffffffu, x, off);
        if (lane >= off) x += u;
    }
    __shared__ int wsum[32];
    if (lane == 31) wsum[wid] = x;
    __syncthreads();
    if (wid == 0) {
        int y = wsum[lane];
#pragma unroll
        for (int off = 1; off < 32; off <<= 1) {
            int u = __shfl_up_sync(0xffffffffu, y, off);
            if (lane >= off) y += u;
        }
        wsum[lane] = y;
    }
    __syncthreads();
    int base = (wid > 0) ? wsum[wid - 1] : 0;
    int incl = base + x;
    if (i < N) g_off[i] = incl - v;
    if (t == SCAN_B - 1) g_bsum[blockIdx.x] = incl;
}

// ---------------------------------------------------------------------------
// 4. Attention scores + fp16 convert. Grid-stride; register tables.
// ---------------------------------------------------------------------------
__global__ void att_kernel(const float* __restrict__ x, int N) {
    int t = threadIdx.x;
    int lane = t & 31;
    int g = lane >> 3, l8 = lane & 7;

    float4 ws0[4], ws1[4], wd0[4], wd1[4];
#pragma unroll
    for (int h = 0; h < 4; h++) {
        const float* ws = g_was + h * 64 + l8 * 8;
        const float* wd = g_wad + h * 64 + l8 * 8;
        ws0[h] = *(const float4*)ws; ws1[h] = *(const float4*)(ws + 4);
        wd0[h] = *(const float4*)wd; wd1[h] = *(const float4*)(wd + 4);
    }

    int warp0 = (blockIdx.x * blockDim.x + t) >> 5;
    int nwarps = (gridDim.x * blockDim.x) >> 5;

    for (int node = warp0 * 4 + g; node < N; node += nwarps * 4) {
        const float* xr = x + (size_t)node * D_IN + l8 * 8;
        float4 v0 = *(const float4*)xr;
        float4 v1 = *(const float4*)(xr + 4);

        __half2 h0 = __floats2half2_rn(v0.x, v0.y);
        __half2 h1 = __floats2half2_rn(v0.z, v0.w);
        __half2 h2 = __floats2half2_rn(v1.x, v1.y);
        __half2 h3 = __floats2half2_rn(v1.z, v1.w);
        uint4 pk = make_uint4(*(uint32_t*)&h0, *(uint32_t*)&h1,
                              *(uint32_t*)&h2, *(uint32_t*)&h3);
        *(uint4*)(g_x16 + (size_t)node * D_IN + l8 * 8) = pk;

        float ps[4], pd[4];
#pragma unroll
        for (int h = 0; h < 4; h++) {
            ps[h] = v0.x * ws0[h].x + v0.y * ws0[h].y + v0.z * ws0[h].z + v0.w * ws0[h].w
                  + v1.x * ws1[h].x + v1.y * ws1[h].y + v1.z * ws1[h].z + v1.w * ws1[h].w;
            pd[h] = v0.x * wd0[h].x + v0.y * wd0[h].y + v0.z * wd0[h].z + v0.w * wd0[h].w
                  + v1.x * wd1[h].x + v1.y * wd1[h].y + v1.z * wd1[h].z + v1.w * wd1[h].w;
        }
#pragma unroll
        for (int off = 4; off > 0; off >>= 1) {
#pragma unroll
            for (int h = 0; h < 4; h++) {
                ps[h] += __shfl_xor_sync(0xffffffffu, ps[h], off, 8);
                pd[h] += __shfl_xor_sync(0xffffffffu, pd[h], off, 8);
            }
        }
        if (l8 == 0) {
            *(float4*)(g_asrc + node * HEADS) = make_float4(ps[0], ps[1], ps[2], ps[3]);
            *(float4*)(g_adst + node * HEADS) = make_float4(pd[0], pd[1], pd[2], pd[3]);
        }
    }
}

// ---------------------------------------------------------------------------
// 3b+3c merged: reduce g_bsum prefix, add base, emit cursors, reset g_cnt.
// ---------------------------------------------------------------------------
__global__ void scan23_kernel(int nb, int N, int E) {
    __shared__ int spart[4];
    int t = threadIdx.x;
    int lane = t & 31, wid = t >> 5;

    int v = (t < 128 && t < blockIdx.x) ? g_bsum[t] : 0;
    if (t < 128) {
#pragma unroll
        for (int off = 16; off > 0; off >>= 1)
            v += __shfl_xor_sync(0xffffffffu, v, off);
        if (lane == 0) spart[wid] = v;
    }
    __syncthreads();
    int base = spart[0] + spart[1] + spart[2] + spart[3];

    int i = blockIdx.x * SCAN_B + t;
    if (i < N) {
        int o = g_off[i] + base;
        g_off[i] = o;
        g_cur[i] = o;
        g_cnt[i] = 0;          // restore invariant for next graph replay
    }
    if (blockIdx.x == 0 && t == 0) g_off[N] = E;
}

// ---------------------------------------------------------------------------
// 5. Scatter src ids into CSR slots (4 edges per thread)
// ---------------------------------------------------------------------------
__global__ void scatter_kernel(const void* __restrict__ ei, int E) {
    int e = (blockIdx.x * blockDim.x + threadIdx.x) * 4;
    if (e >= E) return;
    int is64 = g_is64;
    if (e + 3 < E) {
        int s[4], d[4];
        if (is64) {
            longlong2 ps0 = *(const longlong2*)((const long long*)ei + e);
            longlong2 ps1 = *(const longlong2*)((const long long*)ei + e + 2);
            longlong2 pd0 = *(const longlong2*)((const long long*)ei + (size_t)E + e);
            longlong2 pd1 = *(const longlong2*)((const long long*)ei + (size_t)E + e + 2);
            s[0] = (int)ps0.x; s[1] = (int)ps0.y; s[2] = (int)ps1.x; s[3] = (int)ps1.y;
            d[0] = (int)pd0.x; d[1] = (int)pd0.y; d[2] = (int)pd1.x; d[3] = (int)pd1.y;
        } else {
            int4 ps = *(const int4*)((const int*)ei + e);
            int4 pd = *(const int4*)((const int*)ei + (size_t)E + e);
            s[0] = ps.x; s[1] = ps.y; s[2] = ps.z; s[3] = ps.w;
            d[0] = pd.x; d[1] = pd.y; d[2] = pd.z; d[3] = pd.w;
        }
#pragma unroll
        for (int k = 0; k < 4; k++) {
            int pos = atomicAdd(&g_cur[d[k]], 1);
            g_srclist[pos] = s[k];
        }
    } else {
        for (int k = e; k < E; k++) {
            int s = (int)load_edge(ei, is64, k);
            int d = (int)load_edge(ei, is64, (size_t)E + k);
            int pos = atomicAdd(&g_cur[d], 1);
            g_srclist[pos] = s;
        }
    }
}

// ---------------------------------------------------------------------------
// 6. Aggregate in x-space (r8/r9 proven version).
// ---------------------------------------------------------------------------
__global__ void agg_kernel(int N) {
    __shared__ float4 swe[8][32];
    __shared__ int    ssid[8][32];
    int wl = threadIdx.x >> 5;
    int w = (blockIdx.x * blockDim.x + threadIdx.x) >> 5;
    int lane = threadIdx.x & 31;
    if (w >= N) return;

    __half2* arow = (__half2*)(g_agg + (size_t)w * HC);
    int beg = g_off[w];
    int end = g_off[w + 1];
    if (beg == end) {
        __half2 z = __floats2half2_rn(0.f, 0.f);
#pragma unroll
        for (int h = 0; h < 4; h++) arow[h * 32 + lane] = z;
        return;
    }

    float4 ad4 = *(const float4*)(g_adst + w * HEADS);
    float4 den4 = make_float4(0.f, 0.f, 0.f, 0.f);
    float acc[8];
#pragma unroll
    for (int k = 0; k < 8; k++) acc[k] = 0.f;

    for (int base = beg; base < end; base += 32) {
        int c = min(end - base, 32);
        if (lane < c) {
            int s = g_srclist[base + lane];
            float4 as = *(const float4*)(g_asrc + s * HEADS);
            float4 we;
            we.x = __expf(leaky(as.x + ad4.x));
            we.y = __expf(leaky(as.y + ad4.y));
            we.z = __expf(leaky(as.z + ad4.z));
            we.w = __expf(leaky(as.w + ad4.w));
            den4.x += we.x; den4.y += we.y; den4.z += we.z; den4.w += we.w;
            swe[wl][lane] = we;
            ssid[wl][lane] = s;
        }
        __syncwarp();

        uint32_t x0 = *(const uint32_t*)(g_x16 + (size_t)ssid[wl][0] * D_IN + lane * 2);
        for (int j = 0; j < c; j++) {
            uint32_t x1 = 0;
            if (j + 1 < c)
                x1 = *(const uint32_t*)(g_x16 + (size_t)ssid[wl][j + 1] * D_IN + lane * 2);
            float4 we = swe[wl][j];
            float2 xv = __half22float2(*(__half2*)&x0);
            acc[0] += we.x * xv.x; acc[1] += we.x * xv.y;
            acc[2] += we.y * xv.x; acc[3] += we.y * xv.y;
            acc[4] += we.z * xv.x; acc[5] += we.z * xv.y;
            acc[6] += we.w * xv.x; acc[7] += we.w * xv.y;
            x0 = x1;
        }
        __syncwarp();
    }

#pragma unroll
    for (int off = 16; off > 0; off >>= 1) {
        den4.x += __shfl_xor_sync(0xffffffffu, den4.x, off);
        den4.y += __shfl_xor_sync(0xffffffffu, den4.y, off);
        den4.z += __shfl_xor_sync(0xffffffffu, den4.z, off);
        den4.w += __shfl_xor_sync(0xffffffffu, den4.w, off);
    }
    float ix = 1.f / (den4.x + 1e-16f);
    float iy = 1.f / (den4.y + 1e-16f);
    float iz = 1.f / (den4.z + 1e-16f);
    float iw = 1.f / (den4.w + 1e-16f);
    arow[0 * 32 + lane] = __floats2half2_rn(acc[0] * ix, acc[1] * ix);
    arow[1 * 32 + lane] = __floats2half2_rn(acc[2] * iy, acc[3] * iy);
    arow[2 * 32 + lane] = __floats2half2_rn(acc[4] * iz, acc[5] * iz);
    arow[3 * 32 + lane] = __floats2half2_rn(acc[6] * iw, acc[7] * iw);
}

// ---------------------------------------------------------------------------
// 7. Output GEMM with ldmatrix fragment loads (r9 proven version).
// ---------------------------------------------------------------------------
__global__ void __launch_bounds__(256, 2)
gemm_out_kernel(const float* __restrict__ W, const float* __restrict__ bias,
                float* __restrict__ out, int n) {
    extern __shared__ uint32_t sm[];
    uint32_t* sA = sm;                       // 64 rows x SAP uint32
    __half*  sBh = (__half*)(sm + 64 * SAP); // 64 k-rows x SWN halves

    int t = threadIdx.x;
    int lane = t & 31;
    int wid = t >> 5;
    int wm = wid >> 2;
    int wn = wid & 3;          // head
    int row0 = blockIdx.x * 64;

#pragma unroll
    for (int i = 0; i < 8; i++) {
        int idx = t + i * 256;
        int r = idx >> 5, c4 = idx & 31;
        uint4 v = make_uint4(0, 0, 0, 0);
        if (row0 + r < n) v = *(const uint4*)(g_agg + (size_t)(row0 + r) * HC + c4 * 8);
        uint32_t* p = sA + r * SAP + c4 * 4;
        p[0] = v.x; p[1] = v.y; p[2] = v.z; p[3] = v.w;
    }

#pragma unroll
    for (int i = 0; i < 16; i++) {
        int idx4 = t + i * 256;
        int k = idx4 >> 6, c = (idx4 & 63) * 4;
        float4 v = *(const float4*)(W + (size_t)k * HC + c);
        __half2* q = (__half2*)(sBh + k * SWN + c);
        q[0] = __floats2half2_rn(v.x, v.y);
        q[1] = __floats2half2_rn(v.z, v.w);
    }
    __syncthreads();

    uint32_t smem_base = (uint32_t)__cvta_generic_to_shared(sm);
    uint32_t sB_base = smem_base + 64 * SAP * 4;

    int l8 = lane & 7;
    int lrow8 = (lane >> 3) & 1;
    int lk8 = (lane >> 4) & 1;

    uint32_t aAddr[2];
#pragma unroll
    for (int mt = 0; mt < 2; mt++) {
        int r = wm * 32 + mt * 16 + l8 + lrow8 * 8;
        aAddr[mt] = smem_base + r * (SAP * 4) + (wn * 64 + lk8 * 8) * 2;
    }
    uint32_t bAddr[4];
#pragma unroll
    for (int ntp = 0; ntp < 4; ntp++) {
        int krow = l8 + lrow8 * 8;
        bAddr[ntp] = sB_base + krow * (SWN * 2) + (wn * 64 + ntp * 16 + lk8 * 8) * 2;
    }

    float acc[2][8][4];
#pragma unroll
    for (int mt = 0; mt < 2; mt++)
#pragma unroll
        for (int nt = 0; nt < 8; nt++)
#pragma unroll
            for (int k = 0; k < 4; k++) acc[mt][nt][k] = 0.f;

#pragma unroll
    for (int kc = 0; kc < 4; kc++) {
        uint32_t a[2][4];
#pragma unroll
        for (int mt = 0; mt < 2; mt++) {
            asm volatile(
                "ldmatrix.sync.aligned.m8n8.x4.shared.b16 {%0,%1,%2,%3}, [%4];"
                : "=r"(a[mt][0]), "=r"(a[mt][1]), "=r"(a[mt][2]), "=r"(a[mt][3])
                : "r"(aAddr[mt] + kc * 32));
        }
        uint32_t b[4][4];
#pragma unroll
        for (int ntp = 0; ntp < 4; ntp++) {
            asm volatile(
                "ldmatrix.sync.aligned.m8n8.x4.trans.shared.b16 {%0,%1,%2,%3}, [%4];"
                : "=r"(b[ntp][0]), "=r"(b[ntp][1]), "=r"(b[ntp][2]), "=r"(b[ntp][3])
                : "r"(bAddr[ntp] + kc * 16 * (SWN * 2)));
        }
#pragma unroll
        for (int mt = 0; mt < 2; mt++)
#pragma unroll
            for (int nt = 0; nt < 8; nt++) {
                float* c = acc[mt][nt];
                uint32_t b0 = b[nt >> 1][(nt & 1) * 2 + 0];
                uint32_t b1 = b[nt >> 1][(nt & 1) * 2 + 1];
                asm volatile(
                    "mma.sync.aligned.m16n8k16.row.col.f32.f16.f16.f32 "
                    "{%0,%1,%2,%3}, {%4,%5,%6,%7}, {%8,%9}, {%0,%1,%2,%3};"
                    : "+f"(c[0]), "+f"(c[1]), "+f"(c[2]), "+f"(c[3])
                    : "r"(a[mt][0]), "r"(a[mt][1]), "r"(a[mt][2]), "r"(a[mt][3]),
                      "r"(b0), "r"(b1));
            }
    }

    int qr = lane >> 2;
    int ql = lane & 3;
#pragma unroll
    for (int mt = 0; mt < 2; mt++) {
        int r_lo = row0 + wm * 32 + mt * 16 + qr;
#pragma unroll
        for (int nt = 0; nt < 8; nt++) {
            int col = wn * 64 + nt * 8 + 2 * ql;
            float2 bb = *(const float2*)(bias + col);
            const float* c = acc[mt][nt];
            if (r_lo < n)
                *(float2*)(out + (size_t)r_lo * HC + col) = make_float2(c[0] + bb.x, c[1] + bb.y);
            if (r_lo + 8 < n)
                *(float2*)(out + (size_t)(r_lo + 8) * HC + col) = make_float2(c[2] + bb.x, c[3] + bb.y);
        }
    }
}

// ---------------------------------------------------------------------------
// Launch with fork-join: att runs on a side stream concurrently with the
// CSR build chain. Stream/events created once on the (uncaptured) first call.
// ---------------------------------------------------------------------------
extern "C" void kernel_launch(void* const* d_in, const int* in_sizes, int n_in,
                              void* d_out, int out_size) {
    const float* x        = (const float*)d_in[0];
    const void*  ei       = (const void*)d_in[1];
    const float* W        = (const float*)d_in[2];
    const float* att_src  = (const float*)d_in[3];
    const float* att_dst  = (const float*)d_in[4];
    const float* bias     = (const float*)d_in[5];
    float* out = (float*)d_out;

    int N = in_sizes[0] / D_IN;
    int E = in_sizes[1] / 2;

    static cudaStream_t s2 = nullptr;
    static cudaEvent_t evFork = nullptr, evJoin = nullptr;
    if (s2 == nullptr) {
        cudaStreamCreateWithFlags(&s2, cudaStreamNonBlocking);
        cudaEventCreateWithFlags(&evFork, cudaEventDisableTiming);
        cudaEventCreateWithFlags(&evJoin, cudaEventDisableTiming);
    }

    // init produces g_is64 (count) + tables (att) — both branches depend on it
    init_kernel<<<1, 256>>>(ei, W, att_src, att_dst);

    // Fork: att on s2
    cudaEventRecord(evFork, 0);
    cudaStreamWaitEvent(s2, evFork, 0);
    att_kernel<<<512, 256, 0, s2>>>(x, N);
    cudaEventRecord(evJoin, s2);

    // Main branch: CSR build
    count_kernel<<<(E / 4 + 256) / 256, 256>>>(ei, E);
    int nb = (N + SCAN_B - 1) / SCAN_B;   // 98 <= 128
    scan1_kernel<<<nb, SCAN_B>>>(N);
    scan23_kernel<<<nb, SCAN_B>>>(nb, N, E);
    scatter_kernel<<<(E / 4 + 256) / 256, 256>>>(ei, E);

    // Join: agg needs both att results and the CSR
    cudaStreamWaitEvent(0, evJoin, 0);

    long long agg_threads = (long long)N * 32;
    agg_kernel<<<(int)((agg_threads + 255) / 256), 256>>>(N);

    size_t smem = (size_t)64 * SAP * 4 + (size_t)64 * SWN * 2;          // 66 KB
    cudaFuncSetAttribute(gemm_out_kernel, cudaFuncAttributeMaxDynamicSharedMemorySize, (int)smem);
    gemm_out_kernel<<<(N + 63) / 64, 256, smem>>>(W, bias, out, N);
}

// round 14
// speedup vs baseline: 1.4108x; 1.0219x over previous
#include <cuda_runtime.h>
#include <cuda_fp16.h>
#include <math.h>
#include <float.h>
#include <stdint.h>

// Problem constants (GAT_38585986187787)
#define MAX_NODES 100000
#define MAX_EDGES 1600000
#define D_IN 64
#define HEADS 4
#define HC 256   // HEADS * C_OUT
#define SCAN_B 1024
#define MAX_SCAN_BLOCKS 128

#define SAP 132   // agg smem row stride (uint32): 528B/row -> 4-bank row spacing
#define SWN 264   // W smem row stride (halves):  528B/row -> 4-bank row spacing

// ---------------------------------------------------------------------------
// Device scratch
// ---------------------------------------------------------------------------
__device__ __half g_x16[(size_t)MAX_NODES * D_IN];  // 12.8 MB  x in fp16 (L2-resident)
__device__ __half g_agg[(size_t)MAX_NODES * HC];    // 51.2 MB  normalized weighted sums
__device__ __half g_w16[D_IN * HC];                 // 32 KB    W in fp16 [k][n]
__device__ float g_asrc[MAX_NODES * HEADS];
__device__ float g_adst[MAX_NODES * HEADS];
__device__ float g_was[HEADS * D_IN];               // W_h @ att_src_h
__device__ float g_wad[HEADS * D_IN];               // W_h @ att_dst_h
__device__ int   g_cnt[MAX_NODES];                  // ZERO invariant outside a run
__device__ int   g_off[MAX_NODES + 1];
__device__ int   g_cur[MAX_NODES];
__device__ int   g_srclist[MAX_EDGES];
__device__ int   g_bsum[MAX_SCAN_BLOCKS];
__device__ int   g_is64;

__device__ __forceinline__ long long load_edge(const void* ei, int is64, size_t idx) {
    if (is64) return ((const long long*)ei)[idx];
    return (long long)(((const int*)ei)[idx]);
}

__device__ __forceinline__ float leaky(float v) {
    return (v >= 0.f) ? v : 0.2f * v;
}

// ---------------------------------------------------------------------------
// 1. Init (ONE block): detect dtype + projected attention tables.
// ---------------------------------------------------------------------------
__global__ void init_kernel(const void* ei, const float* __restrict__ W,
                            const float* __restrict__ att_src,
                            const float* __restrict__ att_dst) {
    if (threadIdx.x == 0) {
        const unsigned long long* p = (const unsigned long long*)ei;
        bool ok = true;
#pragma unroll
        for (int i = 0; i < 16; i++) ok = ok && (p[i] < (unsigned long long)MAX_NODES);
        g_is64 = ok ? 1 : 0;
    }
    for (int o = threadIdx.x; o < 2 * HEADS * D_IN; o += blockDim.x) {
        int kind = o >> 8;
        int h = (o >> 6) & 3;
        int c = o & 63;
        const float* av = (kind ? att_dst : att_src) + h * 64;
        float s = 0.f;
#pragma unroll 8
        for (int j = 0; j < 64; j++) s += W[(size_t)c * HC + h * 64 + j] * av[j];
        if (kind) g_wad[h * 64 + c] = s;
        else      g_was[h * 64 + c] = s;
    }
}

// ---------------------------------------------------------------------------
// 1b. W -> fp16 pre-conversion (runs on side stream; hidden under CSR build)
// ---------------------------------------------------------------------------
__global__ void w16_kernel(const float* __restrict__ W) {
    int idx4 = blockIdx.x * blockDim.x + threadIdx.x;   // float4 index
    if (idx4 >= D_IN * HC / 4) return;
    float4 v = ((const float4*)W)[idx4];
    __half2* q = (__half2*)(g_w16 + idx4 * 4);
    q[0] = __floats2half2_rn(v.x, v.y);
    q[1] = __floats2half2_rn(v.z, v.w);
}

// ---------------------------------------------------------------------------
// 2. Count in-degrees (4 edges per thread); g_cnt zero on entry.
// ---------------------------------------------------------------------------
__global__ void count_kernel(const void* __restrict__ ei, int E) {
    int e = (blockIdx.x * blockDim.x + threadIdx.x) * 4;
    if (e >= E) return;
    int is64 = g_is64;
    if (e + 3 < E) {
        int d[4];
        if (is64) {
            longlong2 p0 = *(const longlong2*)((const long long*)ei + (size_t)E + e);
            longlong2 p1 = *(const longlong2*)((const long long*)ei + (size_t)E + e + 2);
            d[0] = (int)p0.x; d[1] = (int)p0.y; d[2] = (int)p1.x; d[3] = (int)p1.y;
        } else {
            int4 p = *(const int4*)((const int*)ei + (size_t)E + e);
            d[0] = p.x; d[1] = p.y; d[2] = p.z; d[3] = p.w;
        }
#pragma unroll
        for (int k = 0; k < 4; k++) atomicAdd(&g_cnt[d[k]], 1);
    } else {
        for (int k = e; k < E; k++)
            atomicAdd(&g_cnt[(int)load_edge(ei, is64, (size_t)E + k)], 1);
    }
}

// ---------------------------------------------------------------------------
// 3a. Block-local exclusive scan -> g_off (local), block sums -> g_bsum
// ---------------------------------------------------------------------------
__global__ void scan1_kernel(int N) {
    int t = threadIdx.x;
    int i = blockIdx.x * SCAN_B + t;
    int lane = t & 31, wid = t >> 5;

    int v = (i < N) ? g_cnt[i] : 0;
    int x = v;
#pragma unroll
    for (int off = 1; off < 32; off <<= 1) {
        int u = __shfl_up_sync(0xffffffffu, x, off);
        if (lane >= off) x += u;
    }
    __shared__ int wsum[32];
    if (lane == 31) wsum[wid] = x;
    __syncthreads();
    if (wid == 0) {
        int y = wsum[lane];
#pragma unroll
        for (int off = 1; off < 32; off <<= 1) {
            int u = __shfl_up_sync(0xffffffffu, y, off);
            if (lane >= off) y += u;
        }
        wsum[lane] = y;
    }
    __syncthreads();
    int base = (wid > 0) ? wsum[wid - 1] : 0;
    int incl = base + x;
    if (i < N) g_off[i] = incl - v;
    if (t == SCAN_B - 1) g_bsum[blockIdx.x] = incl;
}

// ---------------------------------------------------------------------------
// 4. Attention scores + fp16 convert. Grid-stride; register tables.
// ---------------------------------------------------------------------------
__global__ void att_kernel(const float* __restrict__ x, int N) {
    int t = threadIdx.x;
    int lane = t & 31;
    int g = lane >> 3, l8 = lane & 7;

    float4 ws0[4], ws1[4], wd0[4], wd1[4];
#pragma unroll
    for (int h = 0; h < 4; h++) {
        const float* ws = g_was + h * 64 + l8 * 8;
        const float* wd = g_wad + h * 64 + l8 * 8;
        ws0[h] = *(const float4*)ws; ws1[h] = *(const float4*)(ws + 4);
        wd0[h] = *(const float4*)wd; wd1[h] = *(const float4*)(wd + 4);
    }

    int warp0 = (blockIdx.x * blockDim.x + t) >> 5;
    int nwarps = (gridDim.x * blockDim.x) >> 5;

    for (int node = warp0 * 4 + g; node < N; node += nwarps * 4) {
        const float* xr = x + (size_t)node * D_IN + l8 * 8;
        float4 v0 = *(const float4*)xr;
        float4 v1 = *(const float4*)(xr + 4);

        __half2 h0 = __floats2half2_rn(v0.x, v0.y);
        __half2 h1 = __floats2half2_rn(v0.z, v0.w);
        __half2 h2 = __floats2half2_rn(v1.x, v1.y);
        __half2 h3 = __floats2half2_rn(v1.z, v1.w);
        uint4 pk = make_uint4(*(uint32_t*)&h0, *(uint32_t*)&h1,
                              *(uint32_t*)&h2, *(uint32_t*)&h3);
        *(uint4*)(g_x16 + (size_t)node * D_IN + l8 * 8) = pk;

        float ps[4], pd[4];
#pragma unroll
        for (int h = 0; h < 4; h++) {
            ps[h] = v0.x * ws0[h].x + v0.y * ws0[h].y + v0.z * ws0[h].z + v0.w * ws0[h].w
                  + v1.x * ws1[h].x + v1.y * ws1[h].y + v1.z * ws1[h].z + v1.w * ws1[h].w;
            pd[h] = v0.x * wd0[h].x + v0.y * wd0[h].y + v0.z * wd0[h].z + v0.w * wd0[h].w
                  + v1.x * wd1[h].x + v1.y * wd1[h].y + v1.z * wd1[h].z + v1.w * wd1[h].w;
        }
#pragma unroll
        for (int off = 4; off > 0; off >>= 1) {
#pragma unroll
            for (int h = 0; h < 4; h++) {
                ps[h] += __shfl_xor_sync(0xffffffffu, ps[h], off, 8);
                pd[h] += __shfl_xor_sync(0xffffffffu, pd[h], off, 8);
            }
        }
        if (l8 == 0) {
            *(float4*)(g_asrc + node * HEADS) = make_float4(ps[0], ps[1], ps[2], ps[3]);
            *(float4*)(g_adst + node * HEADS) = make_float4(pd[0], pd[1], pd[2], pd[3]);
        }
    }
}

// ---------------------------------------------------------------------------
// 3b+3c merged: reduce g_bsum prefix, add base, emit cursors, reset g_cnt.
// ---------------------------------------------------------------------------
__global__ void scan23_kernel(int nb, int N, int E) {
    __shared__ int spart[4];
    int t = threadIdx.x;
    int lane = t & 31, wid = t >> 5;

    int v = (t < 128 && t < blockIdx.x) ? g_bsum[t] : 0;
    if (t < 128) {
#pragma unroll
        for (int off = 16; off > 0; off >>= 1)
            v += __shfl_xor_sync(0xffffffffu, v, off);
        if (lane == 0) spart[wid] = v;
    }
    __syncthreads();
    int base = spart[0] + spart[1] + spart[2] + spart[3];

    int i = blockIdx.x * SCAN_B + t;
    if (i < N) {
        int o = g_off[i] + base;
        g_off[i] = o;
        g_cur[i] = o;
        g_cnt[i] = 0;          // restore invariant for next graph replay
    }
    if (blockIdx.x == 0 && t == 0) g_off[N] = E;
}

// ---------------------------------------------------------------------------
// 5. Scatter src ids into CSR slots (4 edges per thread)
// ---------------------------------------------------------------------------
__global__ void scatter_kernel(const void* __restrict__ ei, int E) {
    int e = (blockIdx.x * blockDim.x + threadIdx.x) * 4;
    if (e >= E) return;
    int is64 = g_is64;
    if (e + 3 < E) {
        int s[4], d[4];
        if (is64) {
            longlong2 ps0 = *(const longlong2*)((const long long*)ei + e);
            longlong2 ps1 = *(const longlong2*)((const long long*)ei + e + 2);
            longlong2 pd0 = *(const longlong2*)((const long long*)ei + (size_t)E + e);
            longlong2 pd1 = *(const longlong2*)((const long long*)ei + (size_t)E + e + 2);
            s[0] = (int)ps0.x; s[1] = (int)ps0.y; s[2] = (int)ps1.x; s[3] = (int)ps1.y;
            d[0] = (int)pd0.x; d[1] = (int)pd0.y; d[2] = (int)pd1.x; d[3] = (int)pd1.y;
        } else {
            int4 ps = *(const int4*)((const int*)ei + e);
            int4 pd = *(const int4*)((const int*)ei + (size_t)E + e);
            s[0] = ps.x; s[1] = ps.y; s[2] = ps.z; s[3] = ps.w;
            d[0] = pd.x; d[1] = pd.y; d[2] = pd.z; d[3] = pd.w;
        }
#pragma unroll
        for (int k = 0; k < 4; k++) {
            int pos = atomicAdd(&g_cur[d[k]], 1);
            g_srclist[pos] = s[k];
        }
    } else {
        for (int k = e; k < E; k++) {
            int s = (int)load_edge(ei, is64, k);
            int d = (int)load_edge(ei, is64, (size_t)E + k);
            int pos = atomicAdd(&g_cur[d], 1);
            g_srclist[pos] = s;
        }
    }
}

// ---------------------------------------------------------------------------
// 6. Aggregate in x-space (r8/r9 proven version).
// ---------------------------------------------------------------------------
__global__ void agg_kernel(int N) {
    __shared__ float4 swe[8][32];
    __shared__ int    ssid[8][32];
    int wl = threadIdx.x >> 5;
    int w = (blockIdx.x * blockDim.x + threadIdx.x) >> 5;
    int lane = threadIdx.x & 31;
    if (w >= N) return;

    __half2* arow = (__half2*)(g_agg + (size_t)w * HC);
    int beg = g_off[w];
    int end = g_off[w + 1];
    if (beg == end) {
        __half2 z = __floats2half2_rn(0.f, 0.f);
#pragma unroll
        for (int h = 0; h < 4; h++) arow[h * 32 + lane] = z;
        return;
    }

    float4 ad4 = *(const float4*)(g_adst + w * HEADS);
    float4 den4 = make_float4(0.f, 0.f, 0.f, 0.f);
    float acc[8];
#pragma unroll
    for (int k = 0; k < 8; k++) acc[k] = 0.f;

    for (int base = beg; base < end; base += 32) {
        int c = min(end - base, 32);
        if (lane < c) {
            int s = g_srclist[base + lane];
            float4 as = *(const float4*)(g_asrc + s * HEADS);
            float4 we;
            we.x = __expf(leaky(as.x + ad4.x));
            we.y = __expf(leaky(as.y + ad4.y));
            we.z = __expf(leaky(as.z + ad4.z));
            we.w = __expf(leaky(as.w + ad4.w));
            den4.x += we.x; den4.y += we.y; den4.z += we.z; den4.w += we.w;
            swe[wl][lane] = we;
            ssid[wl][lane] = s;
        }
        __syncwarp();

        uint32_t x0 = *(const uint32_t*)(g_x16 + (size_t)ssid[wl][0] * D_IN + lane * 2);
        for (int j = 0; j < c; j++) {
            uint32_t x1 = 0;
            if (j + 1 < c)
                x1 = *(const uint32_t*)(g_x16 + (size_t)ssid[wl][j + 1] * D_IN + lane * 2);
            float4 we = swe[wl][j];
            float2 xv = __half22float2(*(__half2*)&x0);
            acc[0] += we.x * xv.x; acc[1] += we.x * xv.y;
            acc[2] += we.y * xv.x; acc[3] += we.y * xv.y;
            acc[4] += we.z * xv.x; acc[5] += we.z * xv.y;
            acc[6] += we.w * xv.x; acc[7] += we.w * xv.y;
            x0 = x1;
        }
        __syncwarp();
    }

#pragma unroll
    for (int off = 16; off > 0; off >>= 1) {
        den4.x += __shfl_xor_sync(0xffffffffu, den4.x, off);
        den4.y += __shfl_xor_sync(0xffffffffu, den4.y, off);
        den4.z += __shfl_xor_sync(0xffffffffu, den4.z, off);
        den4.w += __shfl_xor_sync(0xffffffffu, den4.w, off);
    }
    float ix = 1.f / (den4.x + 1e-16f);
    float iy = 1.f / (den4.y + 1e-16f);
    float iz = 1.f / (den4.z + 1e-16f);
    float iw = 1.f / (den4.w + 1e-16f);
    arow[0 * 32 + lane] = __floats2half2_rn(acc[0] * ix, acc[1] * ix);
    arow[1 * 32 + lane] = __floats2half2_rn(acc[2] * iy, acc[3] * iy);
    arow[2 * 32 + lane] = __floats2half2_rn(acc[4] * iz, acc[5] * iz);
    arow[3 * 32 + lane] = __floats2half2_rn(acc[6] * iw, acc[7] * iw);
}

// ---------------------------------------------------------------------------
// 7. Output GEMM with ldmatrix fragment loads; B staged from pre-converted
//    fp16 g_w16 via raw uint4 copies (no cvt, half the read traffic).
// ---------------------------------------------------------------------------
__global__ void __launch_bounds__(256, 2)
gemm_out_kernel(const float* __restrict__ bias, float* __restrict__ out, int n) {
    extern __shared__ uint32_t sm[];
    uint32_t* sA = sm;                       // 64 rows x SAP uint32
    __half*  sBh = (__half*)(sm + 64 * SAP); // 64 k-rows x SWN halves

    int t = threadIdx.x;
    int lane = t & 31;
    int wid = t >> 5;
    int wm = wid >> 2;
    int wn = wid & 3;          // head
    int row0 = blockIdx.x * 64;

    // ---- Stage agg tile ----
#pragma unroll
    for (int i = 0; i < 8; i++) {
        int idx = t + i * 256;
        int r = idx >> 5, c4 = idx & 31;
        uint4 v = make_uint4(0, 0, 0, 0);
        if (row0 + r < n) v = *(const uint4*)(g_agg + (size_t)(row0 + r) * HC + c4 * 8);
        uint32_t* p = sA + r * SAP + c4 * 4;
        p[0] = v.x; p[1] = v.y; p[2] = v.z; p[3] = v.w;
    }

    // ---- Stage W (fp16, pre-converted): 64 rows x 32 uint4 per row ----
#pragma unroll
    for (int i = 0; i < 8; i++) {
        int idx = t + i * 256;             // uint4 index
        int k = idx >> 5, c8 = idx & 31;   // c8: group of 8 halves
        uint4 v = *(const uint4*)(g_w16 + k * HC + c8 * 8);
        *(uint4*)(sBh + k * SWN + c8 * 8) = v;
    }
    __syncthreads();

    uint32_t smem_base = (uint32_t)__cvta_generic_to_shared(sm);
    uint32_t sB_base = smem_base + 64 * SAP * 4;

    int l8 = lane & 7;
    int lrow8 = (lane >> 3) & 1;
    int lk8 = (lane >> 4) & 1;

    uint32_t aAddr[2];
#pragma unroll
    for (int mt = 0; mt < 2; mt++) {
        int r = wm * 32 + mt * 16 + l8 + lrow8 * 8;
        aAddr[mt] = smem_base + r * (SAP * 4) + (wn * 64 + lk8 * 8) * 2;
    }
    uint32_t bAddr[4];
#pragma unroll
    for (int ntp = 0; ntp < 4; ntp++) {
        int krow = l8 + lrow8 * 8;
        bAddr[ntp] = sB_base + krow * (SWN * 2) + (wn * 64 + ntp * 16 + lk8 * 8) * 2;
    }

    float acc[2][8][4];
#pragma unroll
    for (int mt = 0; mt < 2; mt++)
#pragma unroll
        for (int nt = 0; nt < 8; nt++)
#pragma unroll
            for (int k = 0; k < 4; k++) acc[mt][nt][k] = 0.f;

#pragma unroll
    for (int kc = 0; kc < 4; kc++) {
        uint32_t a[2][4];
#pragma unroll
        for (int mt = 0; mt < 2; mt++) {
            asm volatile(
                "ldmatrix.sync.aligned.m8n8.x4.shared.b16 {%0,%1,%2,%3}, [%4];"
                : "=r"(a[mt][0]), "=r"(a[mt][1]), "=r"(a[mt][2]), "=r"(a[mt][3])
                : "r"(aAddr[mt] + kc * 32));
        }
        uint32_t b[4][4];
#pragma unroll
        for (int ntp = 0; ntp < 4; ntp++) {
            asm volatile(
                "ldmatrix.sync.aligned.m8n8.x4.trans.shared.b16 {%0,%1,%2,%3}, [%4];"
                : "=r"(b[ntp][0]), "=r"(b[ntp][1]), "=r"(b[ntp][2]), "=r"(b[ntp][3])
                : "r"(bAddr[ntp] + kc * 16 * (SWN * 2)));
        }
#pragma unroll
        for (int mt = 0; mt < 2; mt++)
#pragma unroll
            for (int nt = 0; nt < 8; nt++) {
                float* c = acc[mt][nt];
                uint32_t b0 = b[nt >> 1][(nt & 1) * 2 + 0];
                uint32_t b1 = b[nt >> 1][(nt & 1) * 2 + 1];
                asm volatile(
                    "mma.sync.aligned.m16n8k16.row.col.f32.f16.f16.f32 "
                    "{%0,%1,%2,%3}, {%4,%5,%6,%7}, {%8,%9}, {%0,%1,%2,%3};"
                    : "+f"(c[0]), "+f"(c[1]), "+f"(c[2]), "+f"(c[3])
                    : "r"(a[mt][0]), "r"(a[mt][1]), "r"(a[mt][2]), "r"(a[mt][3]),
                      "r"(b0), "r"(b1));
            }
    }

    int qr = lane >> 2;
    int ql = lane & 3;
#pragma unroll
    for (int mt = 0; mt < 2; mt++) {
        int r_lo = row0 + wm * 32 + mt * 16 + qr;
#pragma unroll
        for (int nt = 0; nt < 8; nt++) {
            int col = wn * 64 + nt * 8 + 2 * ql;
            float2 bb = *(const float2*)(bias + col);
            const float* c = acc[mt][nt];
            if (r_lo < n)
                *(float2*)(out + (size_t)r_lo * HC + col) = make_float2(c[0] + bb.x, c[1] + bb.y);
            if (r_lo + 8 < n)
                *(float2*)(out + (size_t)(r_lo + 8) * HC + col) = make_float2(c[2] + bb.x, c[3] + bb.y);
        }
    }
}

// ---------------------------------------------------------------------------
// Launch with fork-join: att + w16 on a side stream concurrent with CSR build.
// ---------------------------------------------------------------------------
extern "C" void kernel_launch(void* const* d_in, const int* in_sizes, int n_in,
                              void* d_out, int out_size) {
    const float* x        = (const float*)d_in[0];
    const void*  ei       = (const void*)d_in[1];
    const float* W        = (const float*)d_in[2];
    const float* att_src  = (const float*)d_in[3];
    const float* att_dst  = (const float*)d_in[4];
    const float* bias     = (const float*)d_in[5];
    float* out = (float*)d_out;

    int N = in_sizes[0] / D_IN;
    int E = in_sizes[1] / 2;

    static cudaStream_t s2 = nullptr;
    static cudaEvent_t evFork = nullptr, evJoin = nullptr;
    if (s2 == nullptr) {
        cudaStreamCreateWithFlags(&s2, cudaStreamNonBlocking);
        cudaEventCreateWithFlags(&evFork, cudaEventDisableTiming);
        cudaEventCreateWithFlags(&evJoin, cudaEventDisableTiming);
    }

    // init produces g_is64 (count) + tables (att) — both branches depend on it
    init_kernel<<<1, 256>>>(ei, W, att_src, att_dst);

    // Fork: att + w16 on s2
    cudaEventRecord(evFork, 0);
    cudaStreamWaitEvent(s2, evFork, 0);
    att_kernel<<<512, 256, 0, s2>>>(x, N);
    w16_kernel<<<(D_IN * HC / 4 + 255) / 256, 256, 0, s2>>>(W);
    cudaEventRecord(evJoin, s2);

    // Main branch: CSR build
    count_kernel<<<(E / 4 + 256) / 256, 256>>>(ei, E);
    int nb = (N + SCAN_B - 1) / SCAN_B;   // 98 <= 128
    scan1_kernel<<<nb, SCAN_B>>>(N);
    scan23_kernel<<<nb, SCAN_B>>>(nb, N, E);
    scatter_kernel<<<(E / 4 + 256) / 256, 256>>>(ei, E);

    // Join: agg needs att results + CSR; gemm needs w16
    cudaStreamWaitEvent(0, evJoin, 0);

    long long agg_threads = (long long)N * 32;
    agg_kernel<<<(int)((agg_threads + 255) / 256), 256>>>(N);

    size_t smem = (size_t)64 * SAP * 4 + (size_t)64 * SWN * 2;          // 66 KB
    cudaFuncSetAttribute(gemm_out_kernel, cudaFuncAttributeMaxDynamicSharedMemorySize, (int)smem);
    gemm_out_kernel<<<(N + 63) / 64, 256, smem>>>(bias, out, N);
}